// round 1
// baseline (speedup 1.0000x reference)
#include <cuda_runtime.h>
#include <cuda_bf16.h>
#include <math.h>

// Problem constants
#define BATCH 4
#define SEQ   2048
#define DMODEL 768
#define NHEAD 12
#define DHEAD 64
#define DFF   3072
#define MROWS (BATCH*SEQ)          // 8192
#define EPS   1e-5f

// ---------------------------------------------------------------------------
// Scratch (device globals; allocation-free contract)
// ---------------------------------------------------------------------------
__device__ float g_q  [(size_t)MROWS * DMODEL];   // [B,H,S,DK]
__device__ float g_k  [(size_t)MROWS * DMODEL];   // [B,H,S,DK]
__device__ float g_v  [(size_t)MROWS * DMODEL];   // [B,H,S,DK]
__device__ float g_ctx[(size_t)MROWS * DMODEL];   // [B,S,H*DK] row-major
__device__ float g_t1 [(size_t)MROWS * DMODEL];   // pre-LN1
__device__ float g_h  [(size_t)MROWS * DMODEL];   // post-LN1
__device__ float g_f1 [(size_t)MROWS * DFF];      // GELU(h @ w1 + b1)
__device__ float g_t2 [(size_t)MROWS * DMODEL];   // pre-LN2

// ---------------------------------------------------------------------------
// Generic tiled SGEMM: C[M,N] = A[M,K] @ B[K,N] (+bias) (+resid) (GELU)
// BM=128 BN=64 BK=16, 256 threads, 8x4 per thread.
// ---------------------------------------------------------------------------
enum { EP_BIAS = 0, EP_RESID = 1, EP_GELU = 2 };

template<int EPI>
__global__ __launch_bounds__(256)
void gemm_kernel(const float* __restrict__ A, const float* __restrict__ Bm,
                 const float* __restrict__ bias, const float* __restrict__ resid,
                 float* __restrict__ C, int Mdim, int Ndim, int Kdim)
{
    const int BM = 128, BN = 64, BK = 16;
    __shared__ float As[BK][BM];
    __shared__ float Bs[BK][BN];

    const int tid = threadIdx.x;
    const int tx = tid & 15;          // 0..15 (cols)
    const int ty = tid >> 4;          // 0..15 (rows)
    const int row0 = blockIdx.y * BM;
    const int col0 = blockIdx.x * BN;

    float acc[8][4];
    #pragma unroll
    for (int i = 0; i < 8; i++)
        #pragma unroll
        for (int j = 0; j < 4; j++) acc[i][j] = 0.f;

    for (int k0 = 0; k0 < Kdim; k0 += BK) {
        // Load A tile (128x16) — 2 float4 per thread
        {
            const int c4 = tid & 3;       // which float4 along K
            const int r  = tid >> 2;      // 0..63
            #pragma unroll
            for (int it = 0; it < 2; it++) {
                const int rr = r + it * 64;
                float4 v = *(const float4*)(A + (size_t)(row0 + rr) * Kdim + k0 + c4 * 4);
                As[c4*4+0][rr] = v.x;
                As[c4*4+1][rr] = v.y;
                As[c4*4+2][rr] = v.z;
                As[c4*4+3][rr] = v.w;
            }
        }
        // Load B tile (16x64) — 1 float4 per thread
        {
            const int n4 = tid & 15;
            const int c  = tid >> 4;
            float4 v = *(const float4*)(Bm + (size_t)(k0 + c) * Ndim + col0 + n4 * 4);
            *(float4*)&Bs[c][n4 * 4] = v;
        }
        __syncthreads();

        #pragma unroll
        for (int kk = 0; kk < BK; kk++) {
            float4 a0 = *(float4*)&As[kk][ty * 8];
            float4 a1 = *(float4*)&As[kk][ty * 8 + 4];
            float4 bv = *(float4*)&Bs[kk][tx * 4];
            float a[8] = {a0.x, a0.y, a0.z, a0.w, a1.x, a1.y, a1.z, a1.w};
            float b[4] = {bv.x, bv.y, bv.z, bv.w};
            #pragma unroll
            for (int i = 0; i < 8; i++)
                #pragma unroll
                for (int j = 0; j < 4; j++)
                    acc[i][j] += a[i] * b[j];
        }
        __syncthreads();
    }

    #pragma unroll
    for (int i = 0; i < 8; i++) {
        const int m = row0 + ty * 8 + i;
        #pragma unroll
        for (int j = 0; j < 4; j++) {
            const int n = col0 + tx * 4 + j;
            float v = acc[i][j] + bias[n];
            if (EPI == EP_RESID) v += resid[(size_t)m * Ndim + n];
            if (EPI == EP_GELU)  v = 0.5f * v * (1.0f + erff(v * 0.70710678118654752f));
            C[(size_t)m * Ndim + n] = v;
        }
    }
}

// ---------------------------------------------------------------------------
// Fused QKV GEMM: X[8192,768] @ {wq,wk,wv}[768,768] + bias, scattered to
// [B,H,S,DK]. gridDim.z selects the projection.
// ---------------------------------------------------------------------------
__global__ __launch_bounds__(256)
void gemm_qkv_kernel(const float* __restrict__ A,
                     const float* __restrict__ wq, const float* __restrict__ wk,
                     const float* __restrict__ wv,
                     const float* __restrict__ bq, const float* __restrict__ bk,
                     const float* __restrict__ bv,
                     float* __restrict__ oq, float* __restrict__ ok,
                     float* __restrict__ ov)
{
    const int BM = 128, BN = 64, BK = 16;
    const int Kdim = DMODEL, Ndim = DMODEL;
    __shared__ float As[BK][BM];
    __shared__ float Bs[BK][BN];

    const float* __restrict__ Bm = (blockIdx.z == 0) ? wq : (blockIdx.z == 1) ? wk : wv;
    const float* __restrict__ bias = (blockIdx.z == 0) ? bq : (blockIdx.z == 1) ? bk : bv;
    float* __restrict__ out = (blockIdx.z == 0) ? oq : (blockIdx.z == 1) ? ok : ov;

    const int tid = threadIdx.x;
    const int tx = tid & 15;
    const int ty = tid >> 4;
    const int row0 = blockIdx.y * BM;
    const int col0 = blockIdx.x * BN;

    float acc[8][4];
    #pragma unroll
    for (int i = 0; i < 8; i++)
        #pragma unroll
        for (int j = 0; j < 4; j++) acc[i][j] = 0.f;

    for (int k0 = 0; k0 < Kdim; k0 += BK) {
        {
            const int c4 = tid & 3;
            const int r  = tid >> 2;
            #pragma unroll
            for (int it = 0; it < 2; it++) {
                const int rr = r + it * 64;
                float4 v = *(const float4*)(A + (size_t)(row0 + rr) * Kdim + k0 + c4 * 4);
                As[c4*4+0][rr] = v.x;
                As[c4*4+1][rr] = v.y;
                As[c4*4+2][rr] = v.z;
                As[c4*4+3][rr] = v.w;
            }
        }
        {
            const int n4 = tid & 15;
            const int c  = tid >> 4;
            float4 v = *(const float4*)(Bm + (size_t)(k0 + c) * Ndim + col0 + n4 * 4);
            *(float4*)&Bs[c][n4 * 4] = v;
        }
        __syncthreads();

        #pragma unroll
        for (int kk = 0; kk < BK; kk++) {
            float4 a0 = *(float4*)&As[kk][ty * 8];
            float4 a1 = *(float4*)&As[kk][ty * 8 + 4];
            float4 bv4 = *(float4*)&Bs[kk][tx * 4];
            float a[8] = {a0.x, a0.y, a0.z, a0.w, a1.x, a1.y, a1.z, a1.w};
            float b[4] = {bv4.x, bv4.y, bv4.z, bv4.w};
            #pragma unroll
            for (int i = 0; i < 8; i++)
                #pragma unroll
                for (int j = 0; j < 4; j++)
                    acc[i][j] += a[i] * b[j];
        }
        __syncthreads();
    }

    // Scatter epilogue into [B,H,S,DK]
    #pragma unroll
    for (int i = 0; i < 8; i++) {
        const int m = row0 + ty * 8 + i;
        const int b = m >> 11;            // m / SEQ
        const int s = m & (SEQ - 1);
        #pragma unroll
        for (int j = 0; j < 4; j++) {
            const int n = col0 + tx * 4 + j;
            const int h = n >> 6;
            const int d = n & 63;
            out[(((size_t)(b * NHEAD + h) * SEQ + s) * DHEAD) + d] = acc[i][j] + bias[n];
        }
    }
}

// ---------------------------------------------------------------------------
// Flash attention (causal). 1 thread = 1 query row; q/o in registers.
// CTA = 128 threads = 128 query rows of one (b,h). 64-key smem tiles.
// ctx written in [B,S,H*DK] row-major.
// ---------------------------------------------------------------------------
__global__ __launch_bounds__(128)
void attn_kernel(const float* __restrict__ Q, const float* __restrict__ Kt,
                 const float* __restrict__ V, float* __restrict__ ctx)
{
    const int BQ = 128, BKEY = 64;
    __shared__ float Ks[BKEY][DHEAD];
    __shared__ float Vs[BKEY][DHEAD];

    const int bh = blockIdx.y;                 // b*NHEAD + h
    const int b  = bh / NHEAD;
    const int h  = bh % NHEAD;
    const int qrow = blockIdx.x * BQ + threadIdx.x;   // within SEQ

    const float* qptr = Q + ((size_t)bh * SEQ + qrow) * DHEAD;
    float q[DHEAD], o[DHEAD];
    #pragma unroll
    for (int d = 0; d < DHEAD; d++) { q[d] = qptr[d] * 0.125f; o[d] = 0.f; }

    float mx = -1e30f, l = 0.f;
    const int qmax = blockIdx.x * BQ + BQ - 1;
    const int nkb = qmax / BKEY + 1;

    for (int kb = 0; kb < nkb; kb++) {
        const float* kbase = Kt + ((size_t)bh * SEQ + kb * BKEY) * DHEAD;
        const float* vbase = V  + ((size_t)bh * SEQ + kb * BKEY) * DHEAD;
        __syncthreads();
        #pragma unroll
        for (int it = 0; it < 8; it++) {
            const int idx = threadIdx.x + it * 128;   // 0..1023 float4 slots
            const int r = idx >> 4;
            const int c = (idx & 15) * 4;
            *(float4*)&Ks[r][c] = *(const float4*)(kbase + r * DHEAD + c);
            *(float4*)&Vs[r][c] = *(const float4*)(vbase + r * DHEAD + c);
        }
        __syncthreads();

        #pragma unroll
        for (int ch = 0; ch < 4; ch++) {              // 16 keys per chunk
            float s[16];
            float cmax = -1e30f;
            #pragma unroll
            for (int j = 0; j < 16; j++) {
                const int jj = ch * 16 + j;
                float acc = 0.f;
                #pragma unroll
                for (int d = 0; d < DHEAD; d += 4) {
                    float4 kv = *(float4*)&Ks[jj][d];
                    acc += q[d] * kv.x + q[d+1] * kv.y + q[d+2] * kv.z + q[d+3] * kv.w;
                }
                const int key = kb * BKEY + jj;
                s[j] = (key <= qrow) ? acc : -1e30f;
                cmax = fmaxf(cmax, s[j]);
            }
            const float mnew = fmaxf(mx, cmax);
            const float corr = __expf(mx - mnew);
            mx = mnew;
            l *= corr;
            #pragma unroll
            for (int d = 0; d < DHEAD; d++) o[d] *= corr;
            #pragma unroll
            for (int j = 0; j < 16; j++) {
                const float p = __expf(s[j] - mnew);
                l += p;
                const int jj = ch * 16 + j;
                #pragma unroll
                for (int d = 0; d < DHEAD; d += 4) {
                    float4 vv = *(float4*)&Vs[jj][d];
                    o[d]   += p * vv.x;
                    o[d+1] += p * vv.y;
                    o[d+2] += p * vv.z;
                    o[d+3] += p * vv.w;
                }
            }
        }
    }

    const float inv = 1.f / l;
    float* optr = ctx + ((size_t)(b * SEQ + qrow)) * DMODEL + h * DHEAD;
    #pragma unroll
    for (int d = 0; d < DHEAD; d++) optr[d] = o[d] * inv;
}

// ---------------------------------------------------------------------------
// Row-wise LayerNorm over 768 elems. 256 threads/row, two-pass (mean, var).
// ---------------------------------------------------------------------------
__global__ __launch_bounds__(256)
void ln_kernel(const float* __restrict__ X, const float* __restrict__ g,
               const float* __restrict__ be, float* __restrict__ Y)
{
    __shared__ float red[8];
    const int row = blockIdx.x;
    const int tid = threadIdx.x;
    const float* x = X + (size_t)row * DMODEL;

    float v[3];
    float s = 0.f;
    #pragma unroll
    for (int i = 0; i < 3; i++) { v[i] = x[tid + i * 256]; s += v[i]; }

    #pragma unroll
    for (int off = 16; off; off >>= 1) s += __shfl_xor_sync(0xffffffffu, s, off);
    if ((tid & 31) == 0) red[tid >> 5] = s;
    __syncthreads();
    float total = 0.f;
    #pragma unroll
    for (int i = 0; i < 8; i++) total += red[i];
    const float mean = total * (1.0f / DMODEL);
    __syncthreads();

    float s2 = 0.f;
    #pragma unroll
    for (int i = 0; i < 3; i++) { const float d = v[i] - mean; s2 += d * d; }
    #pragma unroll
    for (int off = 16; off; off >>= 1) s2 += __shfl_xor_sync(0xffffffffu, s2, off);
    if ((tid & 31) == 0) red[tid >> 5] = s2;
    __syncthreads();
    float tot2 = 0.f;
    #pragma unroll
    for (int i = 0; i < 8; i++) tot2 += red[i];
    const float rstd = rsqrtf(tot2 * (1.0f / DMODEL) + EPS);

    #pragma unroll
    for (int i = 0; i < 3; i++) {
        const int c = tid + i * 256;
        Y[(size_t)row * DMODEL + c] = (v[i] - mean) * rstd * g[c] + be[c];
    }
}

// ---------------------------------------------------------------------------
// Launch
// ---------------------------------------------------------------------------
static float* sym_addr(const void* sym)
{
    void* p = nullptr;
    cudaGetSymbolAddress(&p, sym);
    return (float*)p;
}

extern "C" void kernel_launch(void* const* d_in, const int* in_sizes, int n_in,
                              void* d_out, int out_size)
{
    const float* x   = (const float*)d_in[0];
    // d_in[1] = mask (causal; implied)
    const float* wq  = (const float*)d_in[2];
    const float* bq  = (const float*)d_in[3];
    const float* wk  = (const float*)d_in[4];
    const float* bk  = (const float*)d_in[5];
    const float* wv  = (const float*)d_in[6];
    const float* bv  = (const float*)d_in[7];
    const float* wo  = (const float*)d_in[8];
    const float* bo  = (const float*)d_in[9];
    const float* g1  = (const float*)d_in[10];
    const float* be1 = (const float*)d_in[11];
    const float* w1  = (const float*)d_in[12];
    const float* b1  = (const float*)d_in[13];
    const float* w2  = (const float*)d_in[14];
    const float* b2  = (const float*)d_in[15];
    const float* g2  = (const float*)d_in[16];
    const float* be2 = (const float*)d_in[17];
    float* out = (float*)d_out;

    float* q   = sym_addr(g_q);
    float* k   = sym_addr(g_k);
    float* v   = sym_addr(g_v);
    float* ctx = sym_addr(g_ctx);
    float* t1  = sym_addr(g_t1);
    float* hh  = sym_addr(g_h);
    float* f1  = sym_addr(g_f1);
    float* t2  = sym_addr(g_t2);

    // 1. QKV projections (scattered to [B,H,S,DK])
    gemm_qkv_kernel<<<dim3(DMODEL/64, MROWS/128, 3), 256>>>(
        x, wq, wk, wv, bq, bk, bv, q, k, v);

    // 2. Causal flash attention -> ctx [B,S,H*DK]
    attn_kernel<<<dim3(SEQ/128, BATCH*NHEAD), 128>>>(q, k, v, ctx);

    // 3. ctx @ wo + bo + x -> t1
    gemm_kernel<EP_RESID><<<dim3(DMODEL/64, MROWS/128), 256>>>(
        ctx, wo, bo, x, t1, MROWS, DMODEL, DMODEL);

    // 4. LN1 -> h
    ln_kernel<<<MROWS, 256>>>(t1, g1, be1, hh);

    // 5. GELU(h @ w1 + b1) -> f1
    gemm_kernel<EP_GELU><<<dim3(DFF/64, MROWS/128), 256>>>(
        hh, w1, b1, nullptr, f1, MROWS, DFF, DMODEL);

    // 6. f1 @ w2 + b2 + h -> t2
    gemm_kernel<EP_RESID><<<dim3(DMODEL/64, MROWS/128), 256>>>(
        f1, w2, b2, hh, t2, MROWS, DMODEL, DFF);

    // 7. LN2 -> out
    ln_kernel<<<MROWS, 256>>>(t2, g2, be2, out);
}

// round 2
// speedup vs baseline: 1.4538x; 1.4538x over previous
#include <cuda_runtime.h>
#include <cuda_bf16.h>
#include <math.h>
#include <stdint.h>

// Problem constants
#define BATCH 4
#define SEQ   2048
#define DMODEL 768
#define NHEAD 12
#define DHEAD 64
#define DFF   3072
#define MROWS (BATCH*SEQ)          // 8192
#define EPS   1e-5f

// ---------------------------------------------------------------------------
// Scratch (device globals; allocation-free contract)
// ---------------------------------------------------------------------------
__device__ float g_q  [(size_t)MROWS * DMODEL];   // [B,S,H*DK]
__device__ float g_k  [(size_t)MROWS * DMODEL];
__device__ float g_v  [(size_t)MROWS * DMODEL];
__device__ float g_ctx[(size_t)MROWS * DMODEL];
__device__ float g_t1 [(size_t)MROWS * DMODEL];
__device__ float g_h  [(size_t)MROWS * DMODEL];
__device__ float g_f1 [(size_t)MROWS * DFF];
__device__ float g_t2 [(size_t)MROWS * DMODEL];

// ---------------------------------------------------------------------------
// tf32 helpers
// ---------------------------------------------------------------------------
__device__ __forceinline__ float f2tf32(float x)
{
    uint32_t u;
    asm("cvt.rna.tf32.f32 %0, %1;" : "=r"(u) : "f"(x));
    return __uint_as_float(u);
}

__device__ __forceinline__ void mma_tf32(float* c, const uint32_t* a, const uint32_t* b)
{
    asm volatile(
        "mma.sync.aligned.m16n8k8.row.col.f32.tf32.tf32.f32 "
        "{%0,%1,%2,%3},{%4,%5,%6,%7},{%8,%9},{%0,%1,%2,%3};\n"
        : "+f"(c[0]), "+f"(c[1]), "+f"(c[2]), "+f"(c[3])
        : "r"(a[0]), "r"(a[1]), "r"(a[2]), "r"(a[3]), "r"(b[0]), "r"(b[1]));
}

// ---------------------------------------------------------------------------
// Tensor-core tf32 GEMM: C[M,N] = A[M,K] @ B[K,N] + bias (+resid) (GELU)
// BM=128 BN=128 BK=16, 256 threads (8 warps, 2x4), warp tile 64x32.
// A/B rounded to tf32 (rna) at smem store. Register-prefetch pipeline.
// ---------------------------------------------------------------------------
enum { EP_BIAS = 0, EP_RESID = 1, EP_GELU = 2 };

template<int EPI>
__global__ __launch_bounds__(256)
void gemm_tc(const float* __restrict__ A, const float* __restrict__ Bm,
             const float* __restrict__ bias, const float* __restrict__ resid,
             float* __restrict__ C, int Ndim, int Kdim)
{
    __shared__ float As[16][132];   // [k][m], pad -> conflict-free frag loads
    __shared__ float Bs[16][132];   // [k][n]

    const int tid  = threadIdx.x;
    const int lane = tid & 31;
    const int warp = tid >> 5;
    const int wm = warp & 1;        // 0..1 -> m offset 64*wm
    const int wn = warp >> 1;       // 0..3 -> n offset 32*wn
    const int g = lane >> 2;        // groupID
    const int q = lane & 3;         // threadID_in_group
    const int row0 = blockIdx.y * 128;
    const int col0 = blockIdx.x * 128;

    // global-load mapping
    const int ar = tid >> 2;        // 0..63 (A row)
    const int ac = tid & 3;         // A float4 col
    const int bn = tid & 31;        // B float4 col
    const int bk = tid >> 5;        // 0..7 (B row)

    float acc[4][4][4];
    #pragma unroll
    for (int i = 0; i < 4; i++)
        #pragma unroll
        for (int j = 0; j < 4; j++)
            #pragma unroll
            for (int r = 0; r < 4; r++) acc[i][j][r] = 0.f;

    float4 ra0, ra1, rb0, rb1;

    #define LDG_TILE(k0)                                                          \
        ra0 = *(const float4*)(A  + (size_t)(row0 + ar)      * Kdim + (k0) + ac*4); \
        ra1 = *(const float4*)(A  + (size_t)(row0 + ar + 64) * Kdim + (k0) + ac*4); \
        rb0 = *(const float4*)(Bm + (size_t)((k0) + bk)     * Ndim + col0 + bn*4); \
        rb1 = *(const float4*)(Bm + (size_t)((k0) + bk + 8) * Ndim + col0 + bn*4);

    #define STS_TILE()                                                        \
        As[ac*4+0][ar]     = f2tf32(ra0.x); As[ac*4+1][ar]     = f2tf32(ra0.y); \
        As[ac*4+2][ar]     = f2tf32(ra0.z); As[ac*4+3][ar]     = f2tf32(ra0.w); \
        As[ac*4+0][ar+64]  = f2tf32(ra1.x); As[ac*4+1][ar+64]  = f2tf32(ra1.y); \
        As[ac*4+2][ar+64]  = f2tf32(ra1.z); As[ac*4+3][ar+64]  = f2tf32(ra1.w); \
        Bs[bk  ][bn*4+0] = f2tf32(rb0.x); Bs[bk  ][bn*4+1] = f2tf32(rb0.y);   \
        Bs[bk  ][bn*4+2] = f2tf32(rb0.z); Bs[bk  ][bn*4+3] = f2tf32(rb0.w);   \
        Bs[bk+8][bn*4+0] = f2tf32(rb1.x); Bs[bk+8][bn*4+1] = f2tf32(rb1.y);   \
        Bs[bk+8][bn*4+2] = f2tf32(rb1.z); Bs[bk+8][bn*4+3] = f2tf32(rb1.w);

    #define COMPUTE_TILE()                                                     \
        _Pragma("unroll")                                                      \
        for (int ks = 0; ks < 16; ks += 8) {                                   \
            uint32_t af[4][4], bf[4][2];                                       \
            _Pragma("unroll")                                                  \
            for (int mt = 0; mt < 4; mt++) {                                   \
                const int m0 = wm*64 + mt*16;                                  \
                af[mt][0] = __float_as_uint(As[ks+q  ][m0+g  ]);               \
                af[mt][1] = __float_as_uint(As[ks+q  ][m0+g+8]);               \
                af[mt][2] = __float_as_uint(As[ks+q+4][m0+g  ]);               \
                af[mt][3] = __float_as_uint(As[ks+q+4][m0+g+8]);               \
            }                                                                  \
            _Pragma("unroll")                                                  \
            for (int nt = 0; nt < 4; nt++) {                                   \
                const int n0 = wn*32 + nt*8;                                   \
                bf[nt][0] = __float_as_uint(Bs[ks+q  ][n0+g]);                 \
                bf[nt][1] = __float_as_uint(Bs[ks+q+4][n0+g]);                 \
            }                                                                  \
            _Pragma("unroll")                                                  \
            for (int mt = 0; mt < 4; mt++)                                     \
                _Pragma("unroll")                                              \
                for (int nt = 0; nt < 4; nt++)                                 \
                    mma_tf32(acc[mt][nt], af[mt], bf[nt]);                     \
        }

    // prologue
    LDG_TILE(0);
    STS_TILE();
    __syncthreads();

    for (int k0 = 16; k0 < Kdim; k0 += 16) {
        LDG_TILE(k0);
        COMPUTE_TILE();
        __syncthreads();
        STS_TILE();
        __syncthreads();
    }
    COMPUTE_TILE();

    #undef LDG_TILE
    #undef STS_TILE
    #undef COMPUTE_TILE

    // epilogue
    #pragma unroll
    for (int mt = 0; mt < 4; mt++) {
        const int mlo = row0 + wm*64 + mt*16 + g;
        #pragma unroll
        for (int nt = 0; nt < 4; nt++) {
            const int n = col0 + wn*32 + nt*8 + 2*q;
            const float b0 = bias[n], b1 = bias[n+1];
            #pragma unroll
            for (int half = 0; half < 2; half++) {
                const int m = mlo + half*8;
                float v0 = acc[mt][nt][half*2+0] + b0;
                float v1 = acc[mt][nt][half*2+1] + b1;
                if (EPI == EP_RESID) {
                    v0 += resid[(size_t)m * Ndim + n];
                    v1 += resid[(size_t)m * Ndim + n + 1];
                }
                if (EPI == EP_GELU) {
                    v0 = 0.5f * v0 * (1.0f + erff(v0 * 0.70710678118654752f));
                    v1 = 0.5f * v1 * (1.0f + erff(v1 * 0.70710678118654752f));
                }
                *(float2*)(C + (size_t)m * Ndim + n) = make_float2(v0, v1);
            }
        }
    }
}

// ---------------------------------------------------------------------------
// Flash attention (causal). Q/K/V in [B,S,H*DK] layout.
// 1 thread = 1 query row; 128 threads/CTA; 64-key smem tiles.
// ---------------------------------------------------------------------------
__global__ __launch_bounds__(128)
void attn_kernel(const float* __restrict__ Q, const float* __restrict__ Kt,
                 const float* __restrict__ V, float* __restrict__ ctx)
{
    const int BQ = 128, BKEY = 64;
    __shared__ float Ks[BKEY][DHEAD];
    __shared__ float Vs[BKEY][DHEAD];

    const int bh = blockIdx.y;
    const int b  = bh / NHEAD;
    const int h  = bh % NHEAD;
    const int qrow = blockIdx.x * BQ + threadIdx.x;

    const float* qptr = Q + ((size_t)(b * SEQ + qrow)) * DMODEL + h * DHEAD;
    float q[DHEAD], o[DHEAD];
    #pragma unroll
    for (int d = 0; d < DHEAD; d++) { q[d] = qptr[d] * 0.125f; o[d] = 0.f; }

    float mx = -1e30f, l = 0.f;
    const int qmax = blockIdx.x * BQ + BQ - 1;
    const int nkb = qmax / BKEY + 1;

    for (int kb = 0; kb < nkb; kb++) {
        const float* kbase = Kt + ((size_t)(b * SEQ + kb * BKEY)) * DMODEL + h * DHEAD;
        const float* vbase = V  + ((size_t)(b * SEQ + kb * BKEY)) * DMODEL + h * DHEAD;
        __syncthreads();
        #pragma unroll
        for (int it = 0; it < 8; it++) {
            const int idx = threadIdx.x + it * 128;
            const int r = idx >> 4;
            const int c = (idx & 15) * 4;
            *(float4*)&Ks[r][c] = *(const float4*)(kbase + (size_t)r * DMODEL + c);
            *(float4*)&Vs[r][c] = *(const float4*)(vbase + (size_t)r * DMODEL + c);
        }
        __syncthreads();

        #pragma unroll
        for (int ch = 0; ch < 4; ch++) {
            float s[16];
            float cmax = -1e30f;
            #pragma unroll
            for (int j = 0; j < 16; j++) {
                const int jj = ch * 16 + j;
                float a = 0.f;
                #pragma unroll
                for (int d = 0; d < DHEAD; d += 4) {
                    float4 kv = *(float4*)&Ks[jj][d];
                    a += q[d] * kv.x + q[d+1] * kv.y + q[d+2] * kv.z + q[d+3] * kv.w;
                }
                const int key = kb * BKEY + jj;
                s[j] = (key <= qrow) ? a : -1e30f;
                cmax = fmaxf(cmax, s[j]);
            }
            const float mnew = fmaxf(mx, cmax);
            const float corr = __expf(mx - mnew);
            mx = mnew;
            l *= corr;
            #pragma unroll
            for (int d = 0; d < DHEAD; d++) o[d] *= corr;
            #pragma unroll
            for (int j = 0; j < 16; j++) {
                const float p = __expf(s[j] - mnew);
                l += p;
                const int jj = ch * 16 + j;
                #pragma unroll
                for (int d = 0; d < DHEAD; d += 4) {
                    float4 vv = *(float4*)&Vs[jj][d];
                    o[d]   += p * vv.x;
                    o[d+1] += p * vv.y;
                    o[d+2] += p * vv.z;
                    o[d+3] += p * vv.w;
                }
            }
        }
    }

    const float inv = 1.f / l;
    float* optr = ctx + ((size_t)(b * SEQ + qrow)) * DMODEL + h * DHEAD;
    #pragma unroll
    for (int d = 0; d < DHEAD; d++) optr[d] = o[d] * inv;
}

// ---------------------------------------------------------------------------
// Row-wise LayerNorm over 768 elems. 256 threads/row.
// ---------------------------------------------------------------------------
__global__ __launch_bounds__(256)
void ln_kernel(const float* __restrict__ X, const float* __restrict__ g,
               const float* __restrict__ be, float* __restrict__ Y)
{
    __shared__ float red[8];
    const int row = blockIdx.x;
    const int tid = threadIdx.x;
    const float* x = X + (size_t)row * DMODEL;

    float v[3];
    float s = 0.f;
    #pragma unroll
    for (int i = 0; i < 3; i++) { v[i] = x[tid + i * 256]; s += v[i]; }

    #pragma unroll
    for (int off = 16; off; off >>= 1) s += __shfl_xor_sync(0xffffffffu, s, off);
    if ((tid & 31) == 0) red[tid >> 5] = s;
    __syncthreads();
    float total = 0.f;
    #pragma unroll
    for (int i = 0; i < 8; i++) total += red[i];
    const float mean = total * (1.0f / DMODEL);
    __syncthreads();

    float s2 = 0.f;
    #pragma unroll
    for (int i = 0; i < 3; i++) { const float d = v[i] - mean; s2 += d * d; }
    #pragma unroll
    for (int off = 16; off; off >>= 1) s2 += __shfl_xor_sync(0xffffffffu, s2, off);
    if ((tid & 31) == 0) red[tid >> 5] = s2;
    __syncthreads();
    float tot2 = 0.f;
    #pragma unroll
    for (int i = 0; i < 8; i++) tot2 += red[i];
    const float rstd = rsqrtf(tot2 * (1.0f / DMODEL) + EPS);

    #pragma unroll
    for (int i = 0; i < 3; i++) {
        const int c = tid + i * 256;
        Y[(size_t)row * DMODEL + c] = (v[i] - mean) * rstd * g[c] + be[c];
    }
}

// ---------------------------------------------------------------------------
// Launch
// ---------------------------------------------------------------------------
static float* sym_addr(const void* sym)
{
    void* p = nullptr;
    cudaGetSymbolAddress(&p, sym);
    return (float*)p;
}

extern "C" void kernel_launch(void* const* d_in, const int* in_sizes, int n_in,
                              void* d_out, int out_size)
{
    const float* x   = (const float*)d_in[0];
    // d_in[1] = mask (causal; implied)
    const float* wq  = (const float*)d_in[2];
    const float* bq  = (const float*)d_in[3];
    const float* wk  = (const float*)d_in[4];
    const float* bk  = (const float*)d_in[5];
    const float* wv  = (const float*)d_in[6];
    const float* bv  = (const float*)d_in[7];
    const float* wo  = (const float*)d_in[8];
    const float* bo  = (const float*)d_in[9];
    const float* g1  = (const float*)d_in[10];
    const float* be1 = (const float*)d_in[11];
    const float* w1  = (const float*)d_in[12];
    const float* b1  = (const float*)d_in[13];
    const float* w2  = (const float*)d_in[14];
    const float* b2  = (const float*)d_in[15];
    const float* g2  = (const float*)d_in[16];
    const float* be2 = (const float*)d_in[17];
    float* out = (float*)d_out;

    float* q   = sym_addr(g_q);
    float* k   = sym_addr(g_k);
    float* v   = sym_addr(g_v);
    float* ctx = sym_addr(g_ctx);
    float* t1  = sym_addr(g_t1);
    float* hh  = sym_addr(g_h);
    float* f1  = sym_addr(g_f1);
    float* t2  = sym_addr(g_t2);

    const dim3 gD(DMODEL/128, MROWS/128);   // 6 x 64
    const dim3 gF(DFF/128,    MROWS/128);   // 24 x 64

    // 1. QKV projections -> [B,S,H*DK]
    gemm_tc<EP_BIAS><<<gD, 256>>>(x, wq, bq, nullptr, q, DMODEL, DMODEL);
    gemm_tc<EP_BIAS><<<gD, 256>>>(x, wk, bk, nullptr, k, DMODEL, DMODEL);
    gemm_tc<EP_BIAS><<<gD, 256>>>(x, wv, bv, nullptr, v, DMODEL, DMODEL);

    // 2. Causal flash attention -> ctx
    attn_kernel<<<dim3(SEQ/128, BATCH*NHEAD), 128>>>(q, k, v, ctx);

    // 3. ctx @ wo + bo + x -> t1
    gemm_tc<EP_RESID><<<gD, 256>>>(ctx, wo, bo, x, t1, DMODEL, DMODEL);

    // 4. LN1 -> h
    ln_kernel<<<MROWS, 256>>>(t1, g1, be1, hh);

    // 5. GELU(h @ w1 + b1) -> f1
    gemm_tc<EP_GELU><<<gF, 256>>>(hh, w1, b1, nullptr, f1, DFF, DMODEL);

    // 6. f1 @ w2 + b2 + h -> t2
    gemm_tc<EP_RESID><<<gD, 256>>>(f1, w2, b2, hh, t2, DMODEL, DFF);

    // 7. LN2 -> out
    ln_kernel<<<MROWS, 256>>>(t2, g2, be2, out);
}

// round 3
// speedup vs baseline: 2.9480x; 2.0278x over previous
#include <cuda_runtime.h>
#include <cuda_bf16.h>
#include <math.h>
#include <stdint.h>

// Problem constants
#define BATCH 4
#define SEQ   2048
#define DMODEL 768
#define NHEAD 12
#define DHEAD 64
#define DFF   3072
#define MROWS (BATCH*SEQ)          // 8192
#define EPS   1e-5f

// ---------------------------------------------------------------------------
// Scratch (device globals; allocation-free contract)
// ---------------------------------------------------------------------------
__device__ float g_q  [(size_t)MROWS * DMODEL];   // [B,S,H*DK]
__device__ float g_k  [(size_t)MROWS * DMODEL];
__device__ float g_v  [(size_t)MROWS * DMODEL];
__device__ float g_ctx[(size_t)MROWS * DMODEL];
__device__ float g_t1 [(size_t)MROWS * DMODEL];
__device__ float g_h  [(size_t)MROWS * DMODEL];
__device__ float g_f1 [(size_t)MROWS * DFF];
__device__ float g_t2 [(size_t)MROWS * DMODEL];

// ---------------------------------------------------------------------------
// tf32 helpers
// ---------------------------------------------------------------------------
__device__ __forceinline__ float f2tf32(float x)
{
    uint32_t u;
    asm("cvt.rna.tf32.f32 %0, %1;" : "=r"(u) : "f"(x));
    return __uint_as_float(u);
}

__device__ __forceinline__ void mma_tf32(float* c, const uint32_t* a, const uint32_t* b)
{
    asm volatile(
        "mma.sync.aligned.m16n8k8.row.col.f32.tf32.tf32.f32 "
        "{%0,%1,%2,%3},{%4,%5,%6,%7},{%8,%9},{%0,%1,%2,%3};\n"
        : "+f"(c[0]), "+f"(c[1]), "+f"(c[2]), "+f"(c[3])
        : "r"(a[0]), "r"(a[1]), "r"(a[2]), "r"(a[3]), "r"(b[0]), "r"(b[1]));
}

// ---------------------------------------------------------------------------
// Tensor-core tf32 GEMM: C[M,N] = A[M,K] @ B[K,N] + bias (+resid) (GELU)
// BM=128 BN=128 BK=16, 256 threads (8 warps, 2x4), warp tile 64x32.
// ---------------------------------------------------------------------------
enum { EP_BIAS = 0, EP_RESID = 1, EP_GELU = 2 };

template<int EPI>
__global__ __launch_bounds__(256)
void gemm_tc(const float* __restrict__ A, const float* __restrict__ Bm,
             const float* __restrict__ bias, const float* __restrict__ resid,
             float* __restrict__ C, int Ndim, int Kdim)
{
    __shared__ float As[16][132];   // [k][m]
    __shared__ float Bs[16][132];   // [k][n]

    const int tid  = threadIdx.x;
    const int lane = tid & 31;
    const int warp = tid >> 5;
    const int wm = warp & 1;
    const int wn = warp >> 1;
    const int g = lane >> 2;
    const int q = lane & 3;
    const int row0 = blockIdx.y * 128;
    const int col0 = blockIdx.x * 128;

    const int ar = tid >> 2;
    const int ac = tid & 3;
    const int bn = tid & 31;
    const int bk = tid >> 5;

    float acc[4][4][4];
    #pragma unroll
    for (int i = 0; i < 4; i++)
        #pragma unroll
        for (int j = 0; j < 4; j++)
            #pragma unroll
            for (int r = 0; r < 4; r++) acc[i][j][r] = 0.f;

    float4 ra0, ra1, rb0, rb1;

    #define LDG_TILE(k0)                                                          \
        ra0 = *(const float4*)(A  + (size_t)(row0 + ar)      * Kdim + (k0) + ac*4); \
        ra1 = *(const float4*)(A  + (size_t)(row0 + ar + 64) * Kdim + (k0) + ac*4); \
        rb0 = *(const float4*)(Bm + (size_t)((k0) + bk)     * Ndim + col0 + bn*4); \
        rb1 = *(const float4*)(Bm + (size_t)((k0) + bk + 8) * Ndim + col0 + bn*4);

    #define STS_TILE()                                                        \
        As[ac*4+0][ar]     = f2tf32(ra0.x); As[ac*4+1][ar]     = f2tf32(ra0.y); \
        As[ac*4+2][ar]     = f2tf32(ra0.z); As[ac*4+3][ar]     = f2tf32(ra0.w); \
        As[ac*4+0][ar+64]  = f2tf32(ra1.x); As[ac*4+1][ar+64]  = f2tf32(ra1.y); \
        As[ac*4+2][ar+64]  = f2tf32(ra1.z); As[ac*4+3][ar+64]  = f2tf32(ra1.w); \
        Bs[bk  ][bn*4+0] = f2tf32(rb0.x); Bs[bk  ][bn*4+1] = f2tf32(rb0.y);   \
        Bs[bk  ][bn*4+2] = f2tf32(rb0.z); Bs[bk  ][bn*4+3] = f2tf32(rb0.w);   \
        Bs[bk+8][bn*4+0] = f2tf32(rb1.x); Bs[bk+8][bn*4+1] = f2tf32(rb1.y);   \
        Bs[bk+8][bn*4+2] = f2tf32(rb1.z); Bs[bk+8][bn*4+3] = f2tf32(rb1.w);

    #define COMPUTE_TILE()                                                     \
        _Pragma("unroll")                                                      \
        for (int ks = 0; ks < 16; ks += 8) {                                   \
            uint32_t af[4][4], bf[4][2];                                       \
            _Pragma("unroll")                                                  \
            for (int mt = 0; mt < 4; mt++) {                                   \
                const int m0 = wm*64 + mt*16;                                  \
                af[mt][0] = __float_as_uint(As[ks+q  ][m0+g  ]);               \
                af[mt][1] = __float_as_uint(As[ks+q  ][m0+g+8]);               \
                af[mt][2] = __float_as_uint(As[ks+q+4][m0+g  ]);               \
                af[mt][3] = __float_as_uint(As[ks+q+4][m0+g+8]);               \
            }                                                                  \
            _Pragma("unroll")                                                  \
            for (int nt = 0; nt < 4; nt++) {                                   \
                const int n0 = wn*32 + nt*8;                                   \
                bf[nt][0] = __float_as_uint(Bs[ks+q  ][n0+g]);                 \
                bf[nt][1] = __float_as_uint(Bs[ks+q+4][n0+g]);                 \
            }                                                                  \
            _Pragma("unroll")                                                  \
            for (int mt = 0; mt < 4; mt++)                                     \
                _Pragma("unroll")                                              \
                for (int nt = 0; nt < 4; nt++)                                 \
                    mma_tf32(acc[mt][nt], af[mt], bf[nt]);                     \
        }

    LDG_TILE(0);
    STS_TILE();
    __syncthreads();

    for (int k0 = 16; k0 < Kdim; k0 += 16) {
        LDG_TILE(k0);
        COMPUTE_TILE();
        __syncthreads();
        STS_TILE();
        __syncthreads();
    }
    COMPUTE_TILE();

    #undef LDG_TILE
    #undef STS_TILE
    #undef COMPUTE_TILE

    #pragma unroll
    for (int mt = 0; mt < 4; mt++) {
        const int mlo = row0 + wm*64 + mt*16 + g;
        #pragma unroll
        for (int nt = 0; nt < 4; nt++) {
            const int n = col0 + wn*32 + nt*8 + 2*q;
            const float b0 = bias[n], b1 = bias[n+1];
            #pragma unroll
            for (int half = 0; half < 2; half++) {
                const int m = mlo + half*8;
                float v0 = acc[mt][nt][half*2+0] + b0;
                float v1 = acc[mt][nt][half*2+1] + b1;
                if (EPI == EP_RESID) {
                    v0 += resid[(size_t)m * Ndim + n];
                    v1 += resid[(size_t)m * Ndim + n + 1];
                }
                if (EPI == EP_GELU) {
                    v0 = 0.5f * v0 * (1.0f + erff(v0 * 0.70710678118654752f));
                    v1 = 0.5f * v1 * (1.0f + erff(v1 * 0.70710678118654752f));
                }
                *(float2*)(C + (size_t)m * Ndim + n) = make_float2(v0, v1);
            }
        }
    }
}

// ---------------------------------------------------------------------------
// Tensor-core flash attention (causal, tf32 mma).
// CTA = 4 warps = 64 query rows of one (b,h). 64-key tiles.
// Warp owns 16 rows; scores/softmax in accumulators; P via per-warp smem.
// ---------------------------------------------------------------------------
#define PQ 68
#define PK 68
#define PV 72
#define PP 68
#define ATTN_SMEM ((64*PQ + 64*PK + 64*PV + 64*PP) * 4)

__global__ __launch_bounds__(128)
void attn_tc(const float* __restrict__ Q, const float* __restrict__ K,
             const float* __restrict__ V, float* __restrict__ ctx)
{
    extern __shared__ float sm[];
    float* Qs = sm;                       // [64][PQ]
    float* Ks = sm + 64*PQ;               // [64][PK]
    float* Vs = sm + 64*(PQ+PK);          // [64][PV]
    float* Ps = sm + 64*(PQ+PK+PV);       // [64][PP]

    const int bh = blockIdx.y;
    const int b  = bh / NHEAD;
    const int h  = bh % NHEAD;
    const int qt = (SEQ/64 - 1) - blockIdx.x;   // heavy CTAs first
    const int tid  = threadIdx.x;
    const int warp = tid >> 5;
    const int lane = tid & 31;
    const int g = lane >> 2;
    const int q = lane & 3;
    const int wrow = warp * 16;

    // cooperative load mapping: 2 threads per row, 8 float4 each
    const int lr = tid >> 1;
    const int lc = (tid & 1) * 8;

    // ---- load Q tile (pre-scaled by 1/8, tf32) ----
    {
        const float* src = Q + ((size_t)(b*SEQ + qt*64 + lr)) * DMODEL + h*DHEAD;
        #pragma unroll
        for (int i = 0; i < 8; i++) {
            float4 v4 = *(const float4*)(src + (lc + i) * 4);
            float* dst = &Qs[lr*PQ + (lc + i)*4];
            dst[0] = f2tf32(v4.x * 0.125f);
            dst[1] = f2tf32(v4.y * 0.125f);
            dst[2] = f2tf32(v4.z * 0.125f);
            dst[3] = f2tf32(v4.w * 0.125f);
        }
    }

    float oacc[8][4];
    #pragma unroll
    for (int nt = 0; nt < 8; nt++)
        #pragma unroll
        for (int e = 0; e < 4; e++) oacc[nt][e] = 0.f;
    float m0 = -1e30f, m1 = -1e30f, l0 = 0.f, l1 = 0.f;

    for (int kb = 0; kb <= qt; kb++) {
        __syncthreads();
        // ---- load K,V tiles (tf32) ----
        {
            const float* ksrc = K + ((size_t)(b*SEQ + kb*64 + lr)) * DMODEL + h*DHEAD;
            const float* vsrc = V + ((size_t)(b*SEQ + kb*64 + lr)) * DMODEL + h*DHEAD;
            #pragma unroll
            for (int i = 0; i < 8; i++) {
                float4 kv = *(const float4*)(ksrc + (lc + i) * 4);
                float* kd = &Ks[lr*PK + (lc + i)*4];
                kd[0] = f2tf32(kv.x); kd[1] = f2tf32(kv.y);
                kd[2] = f2tf32(kv.z); kd[3] = f2tf32(kv.w);
                float4 vv = *(const float4*)(vsrc + (lc + i) * 4);
                float* vd = &Vs[lr*PV + (lc + i)*4];
                vd[0] = f2tf32(vv.x); vd[1] = f2tf32(vv.y);
                vd[2] = f2tf32(vv.z); vd[3] = f2tf32(vv.w);
            }
        }
        __syncthreads();

        // ---- scores: S = Q @ K^T (16x64 per warp) ----
        float sacc[8][4];
        #pragma unroll
        for (int nt = 0; nt < 8; nt++)
            #pragma unroll
            for (int e = 0; e < 4; e++) sacc[nt][e] = 0.f;

        #pragma unroll
        for (int ks = 0; ks < 64; ks += 8) {
            uint32_t a[4];
            a[0] = __float_as_uint(Qs[(wrow+g  )*PQ + ks+q  ]);
            a[1] = __float_as_uint(Qs[(wrow+g+8)*PQ + ks+q  ]);
            a[2] = __float_as_uint(Qs[(wrow+g  )*PQ + ks+q+4]);
            a[3] = __float_as_uint(Qs[(wrow+g+8)*PQ + ks+q+4]);
            #pragma unroll
            for (int nt = 0; nt < 8; nt++) {
                uint32_t bb[2];
                bb[0] = __float_as_uint(Ks[(nt*8+g)*PK + ks+q  ]);
                bb[1] = __float_as_uint(Ks[(nt*8+g)*PK + ks+q+4]);
                mma_tf32(sacc[nt], a, bb);
            }
        }

        // ---- causal mask (diagonal tile only) ----
        if (kb == qt) {
            #pragma unroll
            for (int nt = 0; nt < 8; nt++) {
                const int lcol = nt*8 + 2*q;
                const int r0 = wrow + g, r1 = wrow + g + 8;
                if (lcol     > r0) sacc[nt][0] = -1e30f;
                if (lcol + 1 > r0) sacc[nt][1] = -1e30f;
                if (lcol     > r1) sacc[nt][2] = -1e30f;
                if (lcol + 1 > r1) sacc[nt][3] = -1e30f;
            }
        }

        // ---- online softmax ----
        float rm0 = -1e30f, rm1 = -1e30f;
        #pragma unroll
        for (int nt = 0; nt < 8; nt++) {
            rm0 = fmaxf(rm0, fmaxf(sacc[nt][0], sacc[nt][1]));
            rm1 = fmaxf(rm1, fmaxf(sacc[nt][2], sacc[nt][3]));
        }
        rm0 = fmaxf(rm0, __shfl_xor_sync(0xffffffffu, rm0, 1));
        rm0 = fmaxf(rm0, __shfl_xor_sync(0xffffffffu, rm0, 2));
        rm1 = fmaxf(rm1, __shfl_xor_sync(0xffffffffu, rm1, 1));
        rm1 = fmaxf(rm1, __shfl_xor_sync(0xffffffffu, rm1, 2));

        const float mn0 = fmaxf(m0, rm0);
        const float mn1 = fmaxf(m1, rm1);
        const float c0 = __expf(m0 - mn0);
        const float c1 = __expf(m1 - mn1);
        m0 = mn0; m1 = mn1;

        float s0 = 0.f, s1 = 0.f;
        #pragma unroll
        for (int nt = 0; nt < 8; nt++) {
            float p;
            p = __expf(sacc[nt][0] - mn0); s0 += p; sacc[nt][0] = p;
            p = __expf(sacc[nt][1] - mn0); s0 += p; sacc[nt][1] = p;
            p = __expf(sacc[nt][2] - mn1); s1 += p; sacc[nt][2] = p;
            p = __expf(sacc[nt][3] - mn1); s1 += p; sacc[nt][3] = p;
        }
        s0 += __shfl_xor_sync(0xffffffffu, s0, 1);
        s0 += __shfl_xor_sync(0xffffffffu, s0, 2);
        s1 += __shfl_xor_sync(0xffffffffu, s1, 1);
        s1 += __shfl_xor_sync(0xffffffffu, s1, 2);
        l0 = l0 * c0 + s0;
        l1 = l1 * c1 + s1;

        #pragma unroll
        for (int nt = 0; nt < 8; nt++) {
            oacc[nt][0] *= c0; oacc[nt][1] *= c0;
            oacc[nt][2] *= c1; oacc[nt][3] *= c1;
        }

        // ---- write P (tf32) to per-warp smem slice ----
        #pragma unroll
        for (int nt = 0; nt < 8; nt++) {
            *(float2*)&Ps[(wrow+g  )*PP + nt*8 + 2*q] =
                make_float2(f2tf32(sacc[nt][0]), f2tf32(sacc[nt][1]));
            *(float2*)&Ps[(wrow+g+8)*PP + nt*8 + 2*q] =
                make_float2(f2tf32(sacc[nt][2]), f2tf32(sacc[nt][3]));
        }
        __syncwarp();

        // ---- O += P @ V ----
        #pragma unroll
        for (int ks = 0; ks < 64; ks += 8) {
            uint32_t a[4];
            a[0] = __float_as_uint(Ps[(wrow+g  )*PP + ks+q  ]);
            a[1] = __float_as_uint(Ps[(wrow+g+8)*PP + ks+q  ]);
            a[2] = __float_as_uint(Ps[(wrow+g  )*PP + ks+q+4]);
            a[3] = __float_as_uint(Ps[(wrow+g+8)*PP + ks+q+4]);
            #pragma unroll
            for (int nt = 0; nt < 8; nt++) {
                uint32_t bb[2];
                bb[0] = __float_as_uint(Vs[(ks+q  )*PV + nt*8+g]);
                bb[1] = __float_as_uint(Vs[(ks+q+4)*PV + nt*8+g]);
                mma_tf32(oacc[nt], a, bb);
            }
        }
    }

    // ---- epilogue: normalize and write ctx ----
    const float i0 = 1.f / l0;
    const float i1 = 1.f / l1;
    float* c0p = ctx + ((size_t)(b*SEQ + qt*64 + wrow + g    )) * DMODEL + h*DHEAD;
    float* c1p = ctx + ((size_t)(b*SEQ + qt*64 + wrow + g + 8)) * DMODEL + h*DHEAD;
    #pragma unroll
    for (int nt = 0; nt < 8; nt++) {
        *(float2*)(c0p + nt*8 + 2*q) = make_float2(oacc[nt][0]*i0, oacc[nt][1]*i0);
        *(float2*)(c1p + nt*8 + 2*q) = make_float2(oacc[nt][2]*i1, oacc[nt][3]*i1);
    }
}

// ---------------------------------------------------------------------------
// Row-wise LayerNorm over 768 elems. 256 threads/row.
// ---------------------------------------------------------------------------
__global__ __launch_bounds__(256)
void ln_kernel(const float* __restrict__ X, const float* __restrict__ g,
               const float* __restrict__ be, float* __restrict__ Y)
{
    __shared__ float red[8];
    const int row = blockIdx.x;
    const int tid = threadIdx.x;
    const float* x = X + (size_t)row * DMODEL;

    float v[3];
    float s = 0.f;
    #pragma unroll
    for (int i = 0; i < 3; i++) { v[i] = x[tid + i * 256]; s += v[i]; }

    #pragma unroll
    for (int off = 16; off; off >>= 1) s += __shfl_xor_sync(0xffffffffu, s, off);
    if ((tid & 31) == 0) red[tid >> 5] = s;
    __syncthreads();
    float total = 0.f;
    #pragma unroll
    for (int i = 0; i < 8; i++) total += red[i];
    const float mean = total * (1.0f / DMODEL);
    __syncthreads();

    float s2 = 0.f;
    #pragma unroll
    for (int i = 0; i < 3; i++) { const float d = v[i] - mean; s2 += d * d; }
    #pragma unroll
    for (int off = 16; off; off >>= 1) s2 += __shfl_xor_sync(0xffffffffu, s2, off);
    if ((tid & 31) == 0) red[tid >> 5] = s2;
    __syncthreads();
    float tot2 = 0.f;
    #pragma unroll
    for (int i = 0; i < 8; i++) tot2 += red[i];
    const float rstd = rsqrtf(tot2 * (1.0f / DMODEL) + EPS);

    #pragma unroll
    for (int i = 0; i < 3; i++) {
        const int c = tid + i * 256;
        Y[(size_t)row * DMODEL + c] = (v[i] - mean) * rstd * g[c] + be[c];
    }
}

// ---------------------------------------------------------------------------
// Launch
// ---------------------------------------------------------------------------
static float* sym_addr(const void* sym)
{
    void* p = nullptr;
    cudaGetSymbolAddress(&p, sym);
    return (float*)p;
}

extern "C" void kernel_launch(void* const* d_in, const int* in_sizes, int n_in,
                              void* d_out, int out_size)
{
    const float* x   = (const float*)d_in[0];
    // d_in[1] = mask (causal; implied)
    const float* wq  = (const float*)d_in[2];
    const float* bq  = (const float*)d_in[3];
    const float* wk  = (const float*)d_in[4];
    const float* bk  = (const float*)d_in[5];
    const float* wv  = (const float*)d_in[6];
    const float* bv  = (const float*)d_in[7];
    const float* wo  = (const float*)d_in[8];
    const float* bo  = (const float*)d_in[9];
    const float* g1  = (const float*)d_in[10];
    const float* be1 = (const float*)d_in[11];
    const float* w1  = (const float*)d_in[12];
    const float* b1  = (const float*)d_in[13];
    const float* w2  = (const float*)d_in[14];
    const float* b2  = (const float*)d_in[15];
    const float* g2  = (const float*)d_in[16];
    const float* be2 = (const float*)d_in[17];
    float* out = (float*)d_out;

    float* q   = sym_addr(g_q);
    float* k   = sym_addr(g_k);
    float* v   = sym_addr(g_v);
    float* ctx = sym_addr(g_ctx);
    float* t1  = sym_addr(g_t1);
    float* hh  = sym_addr(g_h);
    float* f1  = sym_addr(g_f1);
    float* t2  = sym_addr(g_t2);

    cudaFuncSetAttribute(attn_tc, cudaFuncAttributeMaxDynamicSharedMemorySize,
                         ATTN_SMEM);

    const dim3 gD(DMODEL/128, MROWS/128);   // 6 x 64
    const dim3 gF(DFF/128,    MROWS/128);   // 24 x 64

    // 1. QKV projections -> [B,S,H*DK]
    gemm_tc<EP_BIAS><<<gD, 256>>>(x, wq, bq, nullptr, q, DMODEL, DMODEL);
    gemm_tc<EP_BIAS><<<gD, 256>>>(x, wk, bk, nullptr, k, DMODEL, DMODEL);
    gemm_tc<EP_BIAS><<<gD, 256>>>(x, wv, bv, nullptr, v, DMODEL, DMODEL);

    // 2. Causal flash attention (tensor cores) -> ctx
    attn_tc<<<dim3(SEQ/64, BATCH*NHEAD), 128, ATTN_SMEM>>>(q, k, v, ctx);

    // 3. ctx @ wo + bo + x -> t1
    gemm_tc<EP_RESID><<<gD, 256>>>(ctx, wo, bo, x, t1, DMODEL, DMODEL);

    // 4. LN1 -> h
    ln_kernel<<<MROWS, 256>>>(t1, g1, be1, hh);

    // 5. GELU(h @ w1 + b1) -> f1
    gemm_tc<EP_GELU><<<gF, 256>>>(hh, w1, b1, nullptr, f1, DFF, DMODEL);

    // 6. f1 @ w2 + b2 + h -> t2
    gemm_tc<EP_RESID><<<gD, 256>>>(f1, w2, b2, hh, t2, DMODEL, DFF);

    // 7. LN2 -> out
    ln_kernel<<<MROWS, 256>>>(t2, g2, be2, out);
}

// round 5
// speedup vs baseline: 3.2065x; 1.0877x over previous
#include <cuda_runtime.h>
#include <cuda_bf16.h>
#include <math.h>
#include <stdint.h>

// Problem constants
#define BATCH 4
#define SEQ   2048
#define DMODEL 768
#define NHEAD 12
#define DHEAD 64
#define DFF   3072
#define MROWS (BATCH*SEQ)          // 8192
#define EPS   1e-5f

// ---------------------------------------------------------------------------
// Scratch (device globals; allocation-free contract)
// ---------------------------------------------------------------------------
__device__ float g_q  [(size_t)MROWS * DMODEL];   // [B,S,H*DK], tf32-rounded, pre-scaled 1/8
__device__ float g_k  [(size_t)MROWS * DMODEL];   // tf32-rounded
__device__ float g_v  [(size_t)MROWS * DMODEL];   // tf32-rounded
__device__ float g_ctx[(size_t)MROWS * DMODEL];
__device__ float g_t1 [(size_t)MROWS * DMODEL];
__device__ float g_h  [(size_t)MROWS * DMODEL];
__device__ float g_f1 [(size_t)MROWS * DFF];
__device__ float g_t2 [(size_t)MROWS * DMODEL];

// ---------------------------------------------------------------------------
// tf32 helpers
// ---------------------------------------------------------------------------
__device__ __forceinline__ float f2tf32(float x)
{
    uint32_t u;
    asm("cvt.rna.tf32.f32 %0, %1;" : "=r"(u) : "f"(x));
    return __uint_as_float(u);
}

__device__ __forceinline__ void mma_tf32(float* c, const uint32_t* a, const uint32_t* b)
{
    asm volatile(
        "mma.sync.aligned.m16n8k8.row.col.f32.tf32.tf32.f32 "
        "{%0,%1,%2,%3},{%4,%5,%6,%7},{%8,%9},{%0,%1,%2,%3};\n"
        : "+f"(c[0]), "+f"(c[1]), "+f"(c[2]), "+f"(c[3])
        : "r"(a[0]), "r"(a[1]), "r"(a[2]), "r"(a[3]), "r"(b[0]), "r"(b[1]));
}

__device__ __forceinline__ uint32_t smem_u32(const void* p)
{
    return (uint32_t)__cvta_generic_to_shared(p);
}

// ---------------------------------------------------------------------------
// Tensor-core tf32 GEMM: C[M,N] = A[M,K] @ B[K,N] + bias (+resid/GELU/tf32)
// BM=128 BN=128 BK=16, 256 threads (8 warps, 2x4), warp tile 64x32.
// Double-buffered smem, register prefetch, 1 sync per k-step.
// ---------------------------------------------------------------------------
enum { EP_BIAS = 0, EP_RESID = 1, EP_GELU = 2, EP_TF32 = 3 };

template<int EPI>
__global__ __launch_bounds__(256)
void gemm_tc(const float* __restrict__ A, const float* __restrict__ Bm,
             const float* __restrict__ bias, const float* __restrict__ resid,
             float* __restrict__ C, int Ndim, int Kdim, float oscale)
{
    __shared__ float As[2][16][132];   // [buf][k][m]
    __shared__ float Bs[2][16][132];   // [buf][k][n]

    const int tid  = threadIdx.x;
    const int lane = tid & 31;
    const int warp = tid >> 5;
    const int wm = warp & 1;
    const int wn = warp >> 1;
    const int g = lane >> 2;
    const int q = lane & 3;
    const int row0 = blockIdx.y * 128;
    const int col0 = blockIdx.x * 128;

    const int ar = tid >> 2;
    const int ac = tid & 3;
    const int bn = tid & 31;
    const int bk = tid >> 5;

    float acc[4][4][4];
    #pragma unroll
    for (int i = 0; i < 4; i++)
        #pragma unroll
        for (int j = 0; j < 4; j++)
            #pragma unroll
            for (int r = 0; r < 4; r++) acc[i][j][r] = 0.f;

    float4 ra0, ra1, rb0, rb1;

    #define LDG_TILE(k0)                                                          \
        ra0 = *(const float4*)(A  + (size_t)(row0 + ar)      * Kdim + (k0) + ac*4); \
        ra1 = *(const float4*)(A  + (size_t)(row0 + ar + 64) * Kdim + (k0) + ac*4); \
        rb0 = *(const float4*)(Bm + (size_t)((k0) + bk)     * Ndim + col0 + bn*4); \
        rb1 = *(const float4*)(Bm + (size_t)((k0) + bk + 8) * Ndim + col0 + bn*4);

    #define STS_TILE(bi)                                                            \
        As[bi][ac*4+0][ar]    = f2tf32(ra0.x); As[bi][ac*4+1][ar]    = f2tf32(ra0.y); \
        As[bi][ac*4+2][ar]    = f2tf32(ra0.z); As[bi][ac*4+3][ar]    = f2tf32(ra0.w); \
        As[bi][ac*4+0][ar+64] = f2tf32(ra1.x); As[bi][ac*4+1][ar+64] = f2tf32(ra1.y); \
        As[bi][ac*4+2][ar+64] = f2tf32(ra1.z); As[bi][ac*4+3][ar+64] = f2tf32(ra1.w); \
        Bs[bi][bk  ][bn*4+0] = f2tf32(rb0.x); Bs[bi][bk  ][bn*4+1] = f2tf32(rb0.y);   \
        Bs[bi][bk  ][bn*4+2] = f2tf32(rb0.z); Bs[bi][bk  ][bn*4+3] = f2tf32(rb0.w);   \
        Bs[bi][bk+8][bn*4+0] = f2tf32(rb1.x); Bs[bi][bk+8][bn*4+1] = f2tf32(rb1.y);   \
        Bs[bi][bk+8][bn*4+2] = f2tf32(rb1.z); Bs[bi][bk+8][bn*4+3] = f2tf32(rb1.w);

    #define COMPUTE_TILE(bi)                                                   \
        _Pragma("unroll")                                                      \
        for (int ks = 0; ks < 16; ks += 8) {                                   \
            uint32_t af[4][4], bf[4][2];                                       \
            _Pragma("unroll")                                                  \
            for (int mt = 0; mt < 4; mt++) {                                   \
                const int m0 = wm*64 + mt*16;                                  \
                af[mt][0] = __float_as_uint(As[bi][ks+q  ][m0+g  ]);           \
                af[mt][1] = __float_as_uint(As[bi][ks+q  ][m0+g+8]);           \
                af[mt][2] = __float_as_uint(As[bi][ks+q+4][m0+g  ]);           \
                af[mt][3] = __float_as_uint(As[bi][ks+q+4][m0+g+8]);           \
            }                                                                  \
            _Pragma("unroll")                                                  \
            for (int nt = 0; nt < 4; nt++) {                                   \
                const int n0 = wn*32 + nt*8;                                   \
                bf[nt][0] = __float_as_uint(Bs[bi][ks+q  ][n0+g]);             \
                bf[nt][1] = __float_as_uint(Bs[bi][ks+q+4][n0+g]);             \
            }                                                                  \
            _Pragma("unroll")                                                  \
            for (int mt = 0; mt < 4; mt++)                                     \
                _Pragma("unroll")                                              \
                for (int nt = 0; nt < 4; nt++)                                 \
                    mma_tf32(acc[mt][nt], af[mt], bf[nt]);                     \
        }

    // prologue
    LDG_TILE(0);
    STS_TILE(0);
    __syncthreads();

    int cur = 0;
    for (int k0 = 16; k0 < Kdim; k0 += 16) {
        LDG_TILE(k0);
        COMPUTE_TILE(cur);
        STS_TILE(cur ^ 1);
        __syncthreads();
        cur ^= 1;
    }
    COMPUTE_TILE(cur);

    #undef LDG_TILE
    #undef STS_TILE
    #undef COMPUTE_TILE

    // epilogue
    #pragma unroll
    for (int mt = 0; mt < 4; mt++) {
        const int mlo = row0 + wm*64 + mt*16 + g;
        #pragma unroll
        for (int nt = 0; nt < 4; nt++) {
            const int n = col0 + wn*32 + nt*8 + 2*q;
            const float b0 = bias[n], b1 = bias[n+1];
            #pragma unroll
            for (int half = 0; half < 2; half++) {
                const int m = mlo + half*8;
                float v0 = acc[mt][nt][half*2+0] + b0;
                float v1 = acc[mt][nt][half*2+1] + b1;
                if (EPI == EP_RESID) {
                    v0 += resid[(size_t)m * Ndim + n];
                    v1 += resid[(size_t)m * Ndim + n + 1];
                }
                if (EPI == EP_GELU) {
                    v0 = 0.5f * v0 * (1.0f + erff(v0 * 0.70710678118654752f));
                    v1 = 0.5f * v1 * (1.0f + erff(v1 * 0.70710678118654752f));
                }
                if (EPI == EP_TF32) {
                    v0 = f2tf32(v0 * oscale);
                    v1 = f2tf32(v1 * oscale);
                }
                *(float2*)(C + (size_t)m * Ndim + n) = make_float2(v0, v1);
            }
        }
    }
}

// ---------------------------------------------------------------------------
// Tensor-core flash attention (causal, tf32 mma).
// CTA = 4 warps = 64 query rows of one (b,h). 64-key tiles.
// Q/K/V already tf32-rounded in gmem (Q pre-scaled 1/8).
// Q in register fragments; K/V via double-buffered cp.async prefetch.
// ---------------------------------------------------------------------------
#define PK 68
#define PV 72
#define PP 68
#define ATTN_SMEM ((2*64*PK + 2*64*PV + 64*PP) * 4)

__global__ __launch_bounds__(128)
void attn_tc(const float* __restrict__ Q, const float* __restrict__ K,
             const float* __restrict__ V, float* __restrict__ ctx)
{
    extern __shared__ float sm[];
    float* Kb[2] = { sm, sm + 64*PK };
    float* Vb[2] = { sm + 2*64*PK, sm + 2*64*PK + 64*PV };
    float* Ps    = sm + 2*64*PK + 2*64*PV;      // [64][PP], also Q staging

    const int bh = blockIdx.y;
    const int b  = bh / NHEAD;
    const int h  = bh % NHEAD;
    const int qt = (SEQ/64 - 1) - blockIdx.x;   // heavy CTAs first
    const int tid  = threadIdx.x;
    const int warp = tid >> 5;
    const int lane = tid & 31;
    const int g = lane >> 2;
    const int q = lane & 3;
    const int wrow = warp * 16;

    // cooperative tile-load mapping: 2 threads per row, 8 float4 each
    const int lr  = tid >> 1;
    const int lcb = (tid & 1) * 8;              // float4 chunk base

    const uint32_t kbu[2] = { smem_u32(Kb[0]), smem_u32(Kb[1]) };
    const uint32_t vbu[2] = { smem_u32(Vb[0]), smem_u32(Vb[1]) };

    #define ISSUE_TILE(kb, sel) do {                                                 \
        const float* kbase = K + ((size_t)(b*SEQ + (kb)*64 + lr))*DMODEL + h*DHEAD;  \
        const float* vbase = V + ((size_t)(b*SEQ + (kb)*64 + lr))*DMODEL + h*DHEAD;  \
        const uint32_t kd = kbu[sel] + (uint32_t)(lr*PK + lcb*4)*4u;                 \
        const uint32_t vd = vbu[sel] + (uint32_t)(lr*PV + lcb*4)*4u;                 \
        _Pragma("unroll")                                                            \
        for (int i = 0; i < 8; i++) {                                                \
            asm volatile("cp.async.cg.shared.global [%0], [%1], 16;\n"               \
                         :: "r"(kd + i*16u), "l"(kbase + lcb*4 + i*4));              \
            asm volatile("cp.async.cg.shared.global [%0], [%1], 16;\n"               \
                         :: "r"(vd + i*16u), "l"(vbase + lcb*4 + i*4));              \
        }                                                                            \
        asm volatile("cp.async.commit_group;\n");                                    \
    } while (0)

    // prefetch first K/V tile
    ISSUE_TILE(0, 0);

    // ---- stage Q through Ps, read fragments into registers ----
    {
        const float* qsrc = Q + ((size_t)(b*SEQ + qt*64 + lr))*DMODEL + h*DHEAD;
        #pragma unroll
        for (int i = 0; i < 8; i++)
            *(float4*)&Ps[lr*PP + (lcb + i)*4] = *(const float4*)(qsrc + (lcb + i)*4);
    }
    __syncthreads();
    uint32_t qf[8][4];
    #pragma unroll
    for (int ks8 = 0; ks8 < 8; ks8++) {
        qf[ks8][0] = __float_as_uint(Ps[(wrow+g  )*PP + ks8*8 + q  ]);
        qf[ks8][1] = __float_as_uint(Ps[(wrow+g+8)*PP + ks8*8 + q  ]);
        qf[ks8][2] = __float_as_uint(Ps[(wrow+g  )*PP + ks8*8 + q+4]);
        qf[ks8][3] = __float_as_uint(Ps[(wrow+g+8)*PP + ks8*8 + q+4]);
    }
    __syncthreads();        // Ps free for P use

    float oacc[8][4];
    #pragma unroll
    for (int nt = 0; nt < 8; nt++)
        #pragma unroll
        for (int e = 0; e < 4; e++) oacc[nt][e] = 0.f;
    float m0 = -1e30f, m1 = -1e30f, l0 = 0.f, l1 = 0.f;

    for (int kb = 0; kb <= qt; kb++) {
        const int cur = kb & 1;
        if (kb < qt) {
            ISSUE_TILE(kb + 1, cur ^ 1);
            asm volatile("cp.async.wait_group 1;\n");
        } else {
            asm volatile("cp.async.wait_group 0;\n");
        }
        __syncthreads();

        const float* Ksm = Kb[cur];
        const float* Vsm = Vb[cur];

        // ---- scores: S = Q @ K^T (16x64 per warp) ----
        float sacc[8][4];
        #pragma unroll
        for (int nt = 0; nt < 8; nt++)
            #pragma unroll
            for (int e = 0; e < 4; e++) sacc[nt][e] = 0.f;

        #pragma unroll
        for (int ks8 = 0; ks8 < 8; ks8++) {
            const int ks = ks8 * 8;
            #pragma unroll
            for (int nt = 0; nt < 8; nt++) {
                uint32_t bb[2];
                bb[0] = __float_as_uint(Ksm[(nt*8+g)*PK + ks+q  ]);
                bb[1] = __float_as_uint(Ksm[(nt*8+g)*PK + ks+q+4]);
                mma_tf32(sacc[nt], qf[ks8], bb);
            }
        }

        // ---- causal mask (diagonal tile only) ----
        if (kb == qt) {
            #pragma unroll
            for (int nt = 0; nt < 8; nt++) {
                const int lcol = nt*8 + 2*q;
                const int r0 = wrow + g, r1 = wrow + g + 8;
                if (lcol     > r0) sacc[nt][0] = -1e30f;
                if (lcol + 1 > r0) sacc[nt][1] = -1e30f;
                if (lcol     > r1) sacc[nt][2] = -1e30f;
                if (lcol + 1 > r1) sacc[nt][3] = -1e30f;
            }
        }

        // ---- online softmax ----
        float rm0 = -1e30f, rm1 = -1e30f;
        #pragma unroll
        for (int nt = 0; nt < 8; nt++) {
            rm0 = fmaxf(rm0, fmaxf(sacc[nt][0], sacc[nt][1]));
            rm1 = fmaxf(rm1, fmaxf(sacc[nt][2], sacc[nt][3]));
        }
        rm0 = fmaxf(rm0, __shfl_xor_sync(0xffffffffu, rm0, 1));
        rm0 = fmaxf(rm0, __shfl_xor_sync(0xffffffffu, rm0, 2));
        rm1 = fmaxf(rm1, __shfl_xor_sync(0xffffffffu, rm1, 1));
        rm1 = fmaxf(rm1, __shfl_xor_sync(0xffffffffu, rm1, 2));

        const float mn0 = fmaxf(m0, rm0);
        const float mn1 = fmaxf(m1, rm1);
        const float c0 = __expf(m0 - mn0);
        const float c1 = __expf(m1 - mn1);
        m0 = mn0; m1 = mn1;

        float s0 = 0.f, s1 = 0.f;
        #pragma unroll
        for (int nt = 0; nt < 8; nt++) {
            float p;
            p = __expf(sacc[nt][0] - mn0); s0 += p; sacc[nt][0] = p;
            p = __expf(sacc[nt][1] - mn0); s0 += p; sacc[nt][1] = p;
            p = __expf(sacc[nt][2] - mn1); s1 += p; sacc[nt][2] = p;
            p = __expf(sacc[nt][3] - mn1); s1 += p; sacc[nt][3] = p;
        }
        s0 += __shfl_xor_sync(0xffffffffu, s0, 1);
        s0 += __shfl_xor_sync(0xffffffffu, s0, 2);
        s1 += __shfl_xor_sync(0xffffffffu, s1, 1);
        s1 += __shfl_xor_sync(0xffffffffu, s1, 2);
        l0 = l0 * c0 + s0;
        l1 = l1 * c1 + s1;

        #pragma unroll
        for (int nt = 0; nt < 8; nt++) {
            oacc[nt][0] *= c0; oacc[nt][1] *= c0;
            oacc[nt][2] *= c1; oacc[nt][3] *= c1;
        }

        // ---- write P (tf32) to per-warp smem slice ----
        #pragma unroll
        for (int nt = 0; nt < 8; nt++) {
            *(float2*)&Ps[(wrow+g  )*PP + nt*8 + 2*q] =
                make_float2(f2tf32(sacc[nt][0]), f2tf32(sacc[nt][1]));
            *(float2*)&Ps[(wrow+g+8)*PP + nt*8 + 2*q] =
                make_float2(f2tf32(sacc[nt][2]), f2tf32(sacc[nt][3]));
        }
        __syncwarp();

        // ---- O += P @ V ----
        #pragma unroll
        for (int ks8 = 0; ks8 < 8; ks8++) {
            const int ks = ks8 * 8;
            uint32_t a[4];
            a[0] = __float_as_uint(Ps[(wrow+g  )*PP + ks+q  ]);
            a[1] = __float_as_uint(Ps[(wrow+g+8)*PP + ks+q  ]);
            a[2] = __float_as_uint(Ps[(wrow+g  )*PP + ks+q+4]);
            a[3] = __float_as_uint(Ps[(wrow+g+8)*PP + ks+q+4]);
            #pragma unroll
            for (int nt = 0; nt < 8; nt++) {
                uint32_t bb[2];
                bb[0] = __float_as_uint(Vsm[(ks+q  )*PV + nt*8+g]);
                bb[1] = __float_as_uint(Vsm[(ks+q+4)*PV + nt*8+g]);
                mma_tf32(oacc[nt], a, bb);
            }
        }
        __syncthreads();    // done reading cur buffers before next overwrite
    }
    #undef ISSUE_TILE

    // ---- epilogue: normalize and write ctx ----
    const float i0 = 1.f / l0;
    const float i1 = 1.f / l1;
    float* c0p = ctx + ((size_t)(b*SEQ + qt*64 + wrow + g    )) * DMODEL + h*DHEAD;
    float* c1p = ctx + ((size_t)(b*SEQ + qt*64 + wrow + g + 8)) * DMODEL + h*DHEAD;
    #pragma unroll
    for (int nt = 0; nt < 8; nt++) {
        *(float2*)(c0p + nt*8 + 2*q) = make_float2(oacc[nt][0]*i0, oacc[nt][1]*i0);
        *(float2*)(c1p + nt*8 + 2*q) = make_float2(oacc[nt][2]*i1, oacc[nt][3]*i1);
    }
}

// ---------------------------------------------------------------------------
// Row-wise LayerNorm over 768 elems. 256 threads/row.
// ---------------------------------------------------------------------------
__global__ __launch_bounds__(256)
void ln_kernel(const float* __restrict__ X, const float* __restrict__ g,
               const float* __restrict__ be, float* __restrict__ Y)
{
    __shared__ float red[8];
    const int row = blockIdx.x;
    const int tid = threadIdx.x;
    const float* x = X + (size_t)row * DMODEL;

    float v[3];
    float s = 0.f;
    #pragma unroll
    for (int i = 0; i < 3; i++) { v[i] = x[tid + i * 256]; s += v[i]; }

    #pragma unroll
    for (int off = 16; off; off >>= 1) s += __shfl_xor_sync(0xffffffffu, s, off);
    if ((tid & 31) == 0) red[tid >> 5] = s;
    __syncthreads();
    float total = 0.f;
    #pragma unroll
    for (int i = 0; i < 8; i++) total += red[i];
    const float mean = total * (1.0f / DMODEL);
    __syncthreads();

    float s2 = 0.f;
    #pragma unroll
    for (int i = 0; i < 3; i++) { const float d = v[i] - mean; s2 += d * d; }
    #pragma unroll
    for (int off = 16; off; off >>= 1) s2 += __shfl_xor_sync(0xffffffffu, s2, off);
    if ((tid & 31) == 0) red[tid >> 5] = s2;
    __syncthreads();
    float tot2 = 0.f;
    #pragma unroll
    for (int i = 0; i < 8; i++) tot2 += red[i];
    const float rstd = rsqrtf(tot2 * (1.0f / DMODEL) + EPS);

    #pragma unroll
    for (int i = 0; i < 3; i++) {
        const int c = tid + i * 256;
        Y[(size_t)row * DMODEL + c] = (v[i] - mean) * rstd * g[c] + be[c];
    }
}

// ---------------------------------------------------------------------------
// Launch
// ---------------------------------------------------------------------------
static float* sym_addr(const void* sym)
{
    void* p = nullptr;
    cudaGetSymbolAddress(&p, sym);
    return (float*)p;
}

extern "C" void kernel_launch(void* const* d_in, const int* in_sizes, int n_in,
                              void* d_out, int out_size)
{
    const float* x   = (const float*)d_in[0];
    // d_in[1] = mask (causal; implied)
    const float* wq  = (const float*)d_in[2];
    const float* bq  = (const float*)d_in[3];
    const float* wk  = (const float*)d_in[4];
    const float* bk  = (const float*)d_in[5];
    const float* wv  = (const float*)d_in[6];
    const float* bv  = (const float*)d_in[7];
    const float* wo  = (const float*)d_in[8];
    const float* bo  = (const float*)d_in[9];
    const float* g1  = (const float*)d_in[10];
    const float* be1 = (const float*)d_in[11];
    const float* w1  = (const float*)d_in[12];
    const float* b1  = (const float*)d_in[13];
    const float* w2  = (const float*)d_in[14];
    const float* b2  = (const float*)d_in[15];
    const float* g2  = (const float*)d_in[16];
    const float* be2 = (const float*)d_in[17];
    float* out = (float*)d_out;

    float* q   = sym_addr(g_q);
    float* k   = sym_addr(g_k);
    float* v   = sym_addr(g_v);
    float* ctx = sym_addr(g_ctx);
    float* t1  = sym_addr(g_t1);
    float* hh  = sym_addr(g_h);
    float* f1  = sym_addr(g_f1);
    float* t2  = sym_addr(g_t2);

    cudaFuncSetAttribute(attn_tc, cudaFuncAttributeMaxDynamicSharedMemorySize,
                         ATTN_SMEM);

    const dim3 gD(DMODEL/128, MROWS/128);   // 6 x 64
    const dim3 gF(DFF/128,    MROWS/128);   // 24 x 64

    // 1. QKV projections -> [B,S,H*DK], tf32-rounded (Q pre-scaled 1/8)
    gemm_tc<EP_TF32><<<gD, 256>>>(x, wq, bq, nullptr, q, DMODEL, DMODEL, 0.125f);
    gemm_tc<EP_TF32><<<gD, 256>>>(x, wk, bk, nullptr, k, DMODEL, DMODEL, 1.0f);
    gemm_tc<EP_TF32><<<gD, 256>>>(x, wv, bv, nullptr, v, DMODEL, DMODEL, 1.0f);

    // 2. Causal flash attention (tensor cores, cp.async pipeline) -> ctx
    attn_tc<<<dim3(SEQ/64, BATCH*NHEAD), 128, ATTN_SMEM>>>(q, k, v, ctx);

    // 3. ctx @ wo + bo + x -> t1
    gemm_tc<EP_RESID><<<gD, 256>>>(ctx, wo, bo, x, t1, DMODEL, DMODEL, 1.0f);

    // 4. LN1 -> h
    ln_kernel<<<MROWS, 256>>>(t1, g1, be1, hh);

    // 5. GELU(h @ w1 + b1) -> f1
    gemm_tc<EP_GELU><<<gF, 256>>>(hh, w1, b1, nullptr, f1, DFF, DMODEL, 1.0f);

    // 6. f1 @ w2 + b2 + h -> t2
    gemm_tc<EP_RESID><<<gD, 256>>>(f1, w2, b2, hh, t2, DMODEL, DFF, 1.0f);

    // 7. LN2 -> out
    ln_kernel<<<MROWS, 256>>>(t2, g2, be2, out);
}

// round 6
// speedup vs baseline: 3.6847x; 1.1491x over previous
#include <cuda_runtime.h>
#include <cuda_bf16.h>
#include <math.h>
#include <stdint.h>

// Problem constants
#define BATCH 4
#define SEQ   2048
#define DMODEL 768
#define NHEAD 12
#define DHEAD 64
#define DFF   3072
#define MROWS (BATCH*SEQ)          // 8192
#define EPS   1e-5f

// ---------------------------------------------------------------------------
// Scratch (device globals; allocation-free contract)
// ---------------------------------------------------------------------------
__device__ float g_q  [(size_t)MROWS * DMODEL];   // tf32, pre-scaled 1/8
__device__ float g_k  [(size_t)MROWS * DMODEL];   // tf32
__device__ float g_v  [(size_t)MROWS * DMODEL];   // tf32
__device__ float g_ctx[(size_t)MROWS * DMODEL];   // tf32 (attn epilogue rounds)
__device__ float g_t1 [(size_t)MROWS * DMODEL];
__device__ float g_h  [(size_t)MROWS * DMODEL];   // full fp32 (residual)
__device__ float g_hr [(size_t)MROWS * DMODEL];   // tf32 (FFN1 A operand)
__device__ float g_f1 [(size_t)MROWS * DFF];      // tf32 (GELU epilogue rounds)
__device__ float g_t2 [(size_t)MROWS * DMODEL];
// pre-rounded operands
__device__ float g_xr [(size_t)MROWS * DMODEL];
__device__ float g_wqr[(size_t)DMODEL * DMODEL];
__device__ float g_wkr[(size_t)DMODEL * DMODEL];
__device__ float g_wvr[(size_t)DMODEL * DMODEL];
__device__ float g_wor[(size_t)DMODEL * DMODEL];
__device__ float g_w1r[(size_t)DMODEL * DFF];
__device__ float g_w2r[(size_t)DFF * DMODEL];

// ---------------------------------------------------------------------------
// tf32 helpers
// ---------------------------------------------------------------------------
__device__ __forceinline__ float f2tf32(float x)
{
    uint32_t u;
    asm("cvt.rna.tf32.f32 %0, %1;" : "=r"(u) : "f"(x));
    return __uint_as_float(u);
}

__device__ __forceinline__ void mma_tf32(float* c, const uint32_t* a, const uint32_t* b)
{
    asm volatile(
        "mma.sync.aligned.m16n8k8.row.col.f32.tf32.tf32.f32 "
        "{%0,%1,%2,%3},{%4,%5,%6,%7},{%8,%9},{%0,%1,%2,%3};\n"
        : "+f"(c[0]), "+f"(c[1]), "+f"(c[2]), "+f"(c[3])
        : "r"(a[0]), "r"(a[1]), "r"(a[2]), "r"(a[3]), "r"(b[0]), "r"(b[1]));
}

__device__ __forceinline__ uint32_t smem_u32(const void* p)
{
    return (uint32_t)__cvta_generic_to_shared(p);
}

#define CPA16(dst, src) \
    asm volatile("cp.async.cg.shared.global [%0], [%1], 16;\n" :: "r"(dst), "l"(src))
#define CPA_COMMIT() asm volatile("cp.async.commit_group;\n")
#define CPA_WAIT1()  asm volatile("cp.async.wait_group 1;\n")
#define CPA_WAIT0()  asm volatile("cp.async.wait_group 0;\n")

// ---------------------------------------------------------------------------
// tf32 rounding prep kernel (grid-stride over float4s)
// ---------------------------------------------------------------------------
__global__ __launch_bounds__(256)
void round_tf32_kernel(const float* __restrict__ src, float* __restrict__ dst, int n4)
{
    const int i = blockIdx.x * blockDim.x + threadIdx.x;
    if (i < n4) {
        float4 v = *((const float4*)src + i);
        v.x = f2tf32(v.x); v.y = f2tf32(v.y);
        v.z = f2tf32(v.z); v.w = f2tf32(v.w);
        *((float4*)dst + i) = v;
    }
}

// ---------------------------------------------------------------------------
// cp.async tf32 GEMM: C[M,N] = A[M,K] @ B[K,N] + bias (+resid / GELU->tf32 /
// tf32). Operands MUST be pre-rounded tf32 in gmem.
// BM=128 BN=128 BK=16, 256 threads (8 warps 2x4, warp tile 64x32).
// 3-stage cp.async pipeline, one __syncthreads per k-iter.
// A smem [m][k] pitch 20, B smem [k][n] pitch 132 (both conflict-free frags).
// ---------------------------------------------------------------------------
enum { EP_RESID = 1, EP_GELU_TF32 = 2, EP_TF32 = 3 };

#define APITCH 20
#define ABUF   (128*APITCH)   // 2560 floats
#define BPITCH 132
#define BBUF   (16*BPITCH)    // 2112 floats
#define GEMM_SMEM ((3*ABUF + 3*BBUF) * 4)

template<int EPI>
__global__ __launch_bounds__(256)
void gemm_ca(const float* __restrict__ A, const float* __restrict__ Bm,
             const float* __restrict__ bias, const float* __restrict__ resid,
             float* __restrict__ C, int Ndim, int Kdim, float oscale)
{
    extern __shared__ float gsm[];
    float* As = gsm;             // [3][128][APITCH]
    float* Bs = gsm + 3*ABUF;    // [3][16][BPITCH]

    const int tid  = threadIdx.x;
    const int lane = tid & 31;
    const int warp = tid >> 5;
    const int wm = warp & 1;
    const int wn = warp >> 1;
    const int g = lane >> 2;
    const int q = lane & 3;
    const int row0 = blockIdx.y * 128;
    const int col0 = blockIdx.x * 128;

    // cp.async mappings
    const int ar = tid >> 1;            // 0..127 A row
    const int ac8 = (tid & 1) * 8;      // 0 or 8 (floats)
    const int br = tid >> 4;            // 0..15 B row
    const int bc8 = (tid & 15) * 8;     // 0..120 (floats)

    const uint32_t asu = smem_u32(As);
    const uint32_t bsu = smem_u32(Bs);

    float acc[4][4][4];
    #pragma unroll
    for (int i = 0; i < 4; i++)
        #pragma unroll
        for (int j = 0; j < 4; j++)
            #pragma unroll
            for (int r = 0; r < 4; r++) acc[i][j][r] = 0.f;

    const int nk = Kdim >> 4;

    #define GISSUE(i, bf_) do {                                                   \
        const int k0_ = (i) << 4;                                                 \
        const float* asrc = A + (size_t)(row0 + ar) * Kdim + k0_ + ac8;           \
        const uint32_t ad = asu + (uint32_t)((bf_)*ABUF + ar*APITCH + ac8) * 4u;  \
        CPA16(ad,       asrc);                                                    \
        CPA16(ad + 16u, asrc + 4);                                                \
        const float* bsrc = Bm + (size_t)(k0_ + br) * Ndim + col0 + bc8;          \
        const uint32_t bd = bsu + (uint32_t)((bf_)*BBUF + br*BPITCH + bc8) * 4u;  \
        CPA16(bd,       bsrc);                                                    \
        CPA16(bd + 16u, bsrc + 4);                                                \
        CPA_COMMIT();                                                             \
    } while (0)

    #define GCOMPUTE(bf_) do {                                                    \
        const float* Ab = As + (bf_)*ABUF;                                        \
        const float* Bb = Bs + (bf_)*BBUF;                                        \
        _Pragma("unroll")                                                         \
        for (int ks = 0; ks < 16; ks += 8) {                                      \
            uint32_t af[4][4], bf2[4][2];                                         \
            _Pragma("unroll")                                                     \
            for (int mt = 0; mt < 4; mt++) {                                      \
                const int m0 = wm*64 + mt*16;                                     \
                af[mt][0] = __float_as_uint(Ab[(m0+g  )*APITCH + ks+q  ]);        \
                af[mt][1] = __float_as_uint(Ab[(m0+g+8)*APITCH + ks+q  ]);        \
                af[mt][2] = __float_as_uint(Ab[(m0+g  )*APITCH + ks+q+4]);        \
                af[mt][3] = __float_as_uint(Ab[(m0+g+8)*APITCH + ks+q+4]);        \
            }                                                                     \
            _Pragma("unroll")                                                     \
            for (int nt = 0; nt < 4; nt++) {                                      \
                const int n0 = wn*32 + nt*8;                                      \
                bf2[nt][0] = __float_as_uint(Bb[(ks+q  )*BPITCH + n0+g]);         \
                bf2[nt][1] = __float_as_uint(Bb[(ks+q+4)*BPITCH + n0+g]);         \
            }                                                                     \
            _Pragma("unroll")                                                     \
            for (int mt = 0; mt < 4; mt++)                                        \
                _Pragma("unroll")                                                 \
                for (int nt = 0; nt < 4; nt++)                                    \
                    mma_tf32(acc[mt][nt], af[mt], bf2[nt]);                       \
        }                                                                         \
    } while (0)

    GISSUE(0, 0);
    GISSUE(1, 1);

    for (int i = 0; i < nk; i++) {
        if (i + 1 < nk) { CPA_WAIT1(); } else { CPA_WAIT0(); }
        __syncthreads();
        const int cb = i % 3;
        GCOMPUTE(cb);
        if (i + 2 < nk) GISSUE(i + 2, (i + 2) % 3);
        __syncthreads();    // all warps done reading buf cb before it is reused
    }

    #undef GISSUE
    #undef GCOMPUTE

    // epilogue
    #pragma unroll
    for (int mt = 0; mt < 4; mt++) {
        const int mlo = row0 + wm*64 + mt*16 + g;
        #pragma unroll
        for (int nt = 0; nt < 4; nt++) {
            const int n = col0 + wn*32 + nt*8 + 2*q;
            const float b0 = bias[n], b1 = bias[n+1];
            #pragma unroll
            for (int half = 0; half < 2; half++) {
                const int m = mlo + half*8;
                float v0 = acc[mt][nt][half*2+0] + b0;
                float v1 = acc[mt][nt][half*2+1] + b1;
                if (EPI == EP_RESID) {
                    v0 += resid[(size_t)m * Ndim + n];
                    v1 += resid[(size_t)m * Ndim + n + 1];
                }
                if (EPI == EP_GELU_TF32) {
                    v0 = f2tf32(0.5f * v0 * (1.0f + erff(v0 * 0.70710678118654752f)));
                    v1 = f2tf32(0.5f * v1 * (1.0f + erff(v1 * 0.70710678118654752f)));
                }
                if (EPI == EP_TF32) {
                    v0 = f2tf32(v0 * oscale);
                    v1 = f2tf32(v1 * oscale);
                }
                *(float2*)(C + (size_t)m * Ndim + n) = make_float2(v0, v1);
            }
        }
    }
}

// ---------------------------------------------------------------------------
// Tensor-core flash attention (causal, tf32 mma).
// CTA = 8 warps = 128 query rows of one (b,h). 64-key tiles, cp.async x2 buf.
// Fully-masked warps skip mma work on diagonal tiles.
// ---------------------------------------------------------------------------
#define PK 68
#define PV 72
#define PP 68
#define ATTN_SMEM ((2*64*PK + 2*64*PV + 128*PP) * 4)

__global__ __launch_bounds__(256, 2)
void attn_tc(const float* __restrict__ Q, const float* __restrict__ K,
             const float* __restrict__ V, float* __restrict__ ctx)
{
    extern __shared__ float sm[];
    float* Kb[2] = { sm, sm + 64*PK };
    float* Vb[2] = { sm + 2*64*PK, sm + 2*64*PK + 64*PV };
    float* Ps    = sm + 2*64*PK + 2*64*PV;      // [128][PP], also Q staging

    const int bh = blockIdx.y;
    const int b  = bh / NHEAD;
    const int h  = bh % NHEAD;
    const int qt = (SEQ/128 - 1) - blockIdx.x;  // heavy CTAs first
    const int tid  = threadIdx.x;
    const int warp = tid >> 5;
    const int lane = tid & 31;
    const int g = lane >> 2;
    const int q = lane & 3;
    const int wrow = warp * 16;                 // 0..112
    const int qbase = qt * 128;

    // K/V tile load mapping: 4 threads per row, 4 float4 each
    const int lr = tid >> 2;                    // 0..63
    const int cb = (tid & 3) * 4;               // float4 chunk base

    const uint32_t kbu[2] = { smem_u32(Kb[0]), smem_u32(Kb[1]) };
    const uint32_t vbu[2] = { smem_u32(Vb[0]), smem_u32(Vb[1]) };

    #define ISSUE_TILE(kb, sel) do {                                                 \
        const float* kbase = K + ((size_t)(b*SEQ + (kb)*64 + lr))*DMODEL + h*DHEAD;  \
        const float* vbase = V + ((size_t)(b*SEQ + (kb)*64 + lr))*DMODEL + h*DHEAD;  \
        const uint32_t kd = kbu[sel] + (uint32_t)(lr*PK)*4u + (uint32_t)cb*16u;      \
        const uint32_t vd = vbu[sel] + (uint32_t)(lr*PV)*4u + (uint32_t)cb*16u;      \
        _Pragma("unroll")                                                            \
        for (int i = 0; i < 4; i++) {                                                \
            CPA16(kd + i*16u, kbase + (cb + i)*4);                                   \
            CPA16(vd + i*16u, vbase + (cb + i)*4);                                   \
        }                                                                            \
        CPA_COMMIT();                                                                \
    } while (0)

    ISSUE_TILE(0, 0);

    // ---- stage Q (128 rows) through Ps, read fragments into registers ----
    {
        const int qlr = tid >> 1;
        const int qlc = (tid & 1) * 8;
        const float* qsrc = Q + ((size_t)(b*SEQ + qbase + qlr))*DMODEL + h*DHEAD;
        #pragma unroll
        for (int i = 0; i < 8; i++)
            *(float4*)&Ps[qlr*PP + (qlc + i)*4] = *(const float4*)(qsrc + (qlc + i)*4);
    }
    __syncthreads();
    uint32_t qf[8][4];
    #pragma unroll
    for (int ks8 = 0; ks8 < 8; ks8++) {
        qf[ks8][0] = __float_as_uint(Ps[(wrow+g  )*PP + ks8*8 + q  ]);
        qf[ks8][1] = __float_as_uint(Ps[(wrow+g+8)*PP + ks8*8 + q  ]);
        qf[ks8][2] = __float_as_uint(Ps[(wrow+g  )*PP + ks8*8 + q+4]);
        qf[ks8][3] = __float_as_uint(Ps[(wrow+g+8)*PP + ks8*8 + q+4]);
    }
    __syncthreads();

    float oacc[8][4];
    #pragma unroll
    for (int nt = 0; nt < 8; nt++)
        #pragma unroll
        for (int e = 0; e < 4; e++) oacc[nt][e] = 0.f;
    float m0 = -1e30f, m1 = -1e30f, l0 = 0.f, l1 = 0.f;

    const int nkb = 2*qt + 2;

    for (int kb = 0; kb < nkb; kb++) {
        const int cur = kb & 1;
        if (kb + 1 < nkb) {
            ISSUE_TILE(kb + 1, cur ^ 1);
            CPA_WAIT1();
        } else {
            CPA_WAIT0();
        }
        __syncthreads();

        // skip entirely masked tiles for this warp's rows
        const bool skip = (kb*64) > (qbase + wrow + 15);
        if (!skip) {
            const float* Ksm = Kb[cur];
            const float* Vsm = Vb[cur];

            // ---- scores: S = Q @ K^T (16x64 per warp) ----
            float sacc[8][4];
            #pragma unroll
            for (int nt = 0; nt < 8; nt++)
                #pragma unroll
                for (int e = 0; e < 4; e++) sacc[nt][e] = 0.f;

            #pragma unroll
            for (int ks8 = 0; ks8 < 8; ks8++) {
                const int ks = ks8 * 8;
                #pragma unroll
                for (int nt = 0; nt < 8; nt++) {
                    uint32_t bb[2];
                    bb[0] = __float_as_uint(Ksm[(nt*8+g)*PK + ks+q  ]);
                    bb[1] = __float_as_uint(Ksm[(nt*8+g)*PK + ks+q+4]);
                    mma_tf32(sacc[nt], qf[ks8], bb);
                }
            }

            // ---- causal mask (partial tiles only) ----
            if (kb*64 + 63 > qbase + wrow) {
                const int r0 = qbase + wrow + g;
                const int r1 = r0 + 8;
                #pragma unroll
                for (int nt = 0; nt < 8; nt++) {
                    const int colg = kb*64 + nt*8 + 2*q;
                    if (colg     > r0) sacc[nt][0] = -1e30f;
                    if (colg + 1 > r0) sacc[nt][1] = -1e30f;
                    if (colg     > r1) sacc[nt][2] = -1e30f;
                    if (colg + 1 > r1) sacc[nt][3] = -1e30f;
                }
            }

            // ---- online softmax ----
            float rm0 = -1e30f, rm1 = -1e30f;
            #pragma unroll
            for (int nt = 0; nt < 8; nt++) {
                rm0 = fmaxf(rm0, fmaxf(sacc[nt][0], sacc[nt][1]));
                rm1 = fmaxf(rm1, fmaxf(sacc[nt][2], sacc[nt][3]));
            }
            rm0 = fmaxf(rm0, __shfl_xor_sync(0xffffffffu, rm0, 1));
            rm0 = fmaxf(rm0, __shfl_xor_sync(0xffffffffu, rm0, 2));
            rm1 = fmaxf(rm1, __shfl_xor_sync(0xffffffffu, rm1, 1));
            rm1 = fmaxf(rm1, __shfl_xor_sync(0xffffffffu, rm1, 2));

            const float mn0 = fmaxf(m0, rm0);
            const float mn1 = fmaxf(m1, rm1);
            const float c0 = __expf(m0 - mn0);
            const float c1 = __expf(m1 - mn1);
            m0 = mn0; m1 = mn1;

            float s0 = 0.f, s1 = 0.f;
            #pragma unroll
            for (int nt = 0; nt < 8; nt++) {
                float p;
                p = __expf(sacc[nt][0] - mn0); s0 += p; sacc[nt][0] = p;
                p = __expf(sacc[nt][1] - mn0); s0 += p; sacc[nt][1] = p;
                p = __expf(sacc[nt][2] - mn1); s1 += p; sacc[nt][2] = p;
                p = __expf(sacc[nt][3] - mn1); s1 += p; sacc[nt][3] = p;
            }
            s0 += __shfl_xor_sync(0xffffffffu, s0, 1);
            s0 += __shfl_xor_sync(0xffffffffu, s0, 2);
            s1 += __shfl_xor_sync(0xffffffffu, s1, 1);
            s1 += __shfl_xor_sync(0xffffffffu, s1, 2);
            l0 = l0 * c0 + s0;
            l1 = l1 * c1 + s1;

            #pragma unroll
            for (int nt = 0; nt < 8; nt++) {
                oacc[nt][0] *= c0; oacc[nt][1] *= c0;
                oacc[nt][2] *= c1; oacc[nt][3] *= c1;
            }

            // ---- write P (tf32) to per-warp smem slice ----
            #pragma unroll
            for (int nt = 0; nt < 8; nt++) {
                *(float2*)&Ps[(wrow+g  )*PP + nt*8 + 2*q] =
                    make_float2(f2tf32(sacc[nt][0]), f2tf32(sacc[nt][1]));
                *(float2*)&Ps[(wrow+g+8)*PP + nt*8 + 2*q] =
                    make_float2(f2tf32(sacc[nt][2]), f2tf32(sacc[nt][3]));
            }
            __syncwarp();

            // ---- O += P @ V ----
            #pragma unroll
            for (int ks8 = 0; ks8 < 8; ks8++) {
                const int ks = ks8 * 8;
                uint32_t a[4];
                a[0] = __float_as_uint(Ps[(wrow+g  )*PP + ks+q  ]);
                a[1] = __float_as_uint(Ps[(wrow+g+8)*PP + ks+q  ]);
                a[2] = __float_as_uint(Ps[(wrow+g  )*PP + ks+q+4]);
                a[3] = __float_as_uint(Ps[(wrow+g+8)*PP + ks+q+4]);
                #pragma unroll
                for (int nt = 0; nt < 8; nt++) {
                    uint32_t bb[2];
                    bb[0] = __float_as_uint(Vsm[(ks+q  )*PV + nt*8+g]);
                    bb[1] = __float_as_uint(Vsm[(ks+q+4)*PV + nt*8+g]);
                    mma_tf32(oacc[nt], a, bb);
                }
            }
        }
        __syncthreads();    // everyone done with cur buffers before overwrite
    }
    #undef ISSUE_TILE

    // ---- epilogue: normalize, tf32-round, write ctx ----
    const float i0 = 1.f / l0;
    const float i1 = 1.f / l1;
    float* c0p = ctx + ((size_t)(b*SEQ + qbase + wrow + g    )) * DMODEL + h*DHEAD;
    float* c1p = ctx + ((size_t)(b*SEQ + qbase + wrow + g + 8)) * DMODEL + h*DHEAD;
    #pragma unroll
    for (int nt = 0; nt < 8; nt++) {
        *(float2*)(c0p + nt*8 + 2*q) =
            make_float2(f2tf32(oacc[nt][0]*i0), f2tf32(oacc[nt][1]*i0));
        *(float2*)(c1p + nt*8 + 2*q) =
            make_float2(f2tf32(oacc[nt][2]*i1), f2tf32(oacc[nt][3]*i1));
    }
}

// ---------------------------------------------------------------------------
// Row-wise LayerNorm over 768 elems. 256 threads/row.
// Optional second output Yr = tf32-rounded copy (GEMM A operand).
// ---------------------------------------------------------------------------
__global__ __launch_bounds__(256)
void ln_kernel(const float* __restrict__ X, const float* __restrict__ g,
               const float* __restrict__ be, float* __restrict__ Y,
               float* __restrict__ Yr)
{
    __shared__ float red[8];
    const int row = blockIdx.x;
    const int tid = threadIdx.x;
    const float* x = X + (size_t)row * DMODEL;

    float v[3];
    float s = 0.f;
    #pragma unroll
    for (int i = 0; i < 3; i++) { v[i] = x[tid + i * 256]; s += v[i]; }

    #pragma unroll
    for (int off = 16; off; off >>= 1) s += __shfl_xor_sync(0xffffffffu, s, off);
    if ((tid & 31) == 0) red[tid >> 5] = s;
    __syncthreads();
    float total = 0.f;
    #pragma unroll
    for (int i = 0; i < 8; i++) total += red[i];
    const float mean = total * (1.0f / DMODEL);
    __syncthreads();

    float s2 = 0.f;
    #pragma unroll
    for (int i = 0; i < 3; i++) { const float d = v[i] - mean; s2 += d * d; }
    #pragma unroll
    for (int off = 16; off; off >>= 1) s2 += __shfl_xor_sync(0xffffffffu, s2, off);
    if ((tid & 31) == 0) red[tid >> 5] = s2;
    __syncthreads();
    float tot2 = 0.f;
    #pragma unroll
    for (int i = 0; i < 8; i++) tot2 += red[i];
    const float rstd = rsqrtf(tot2 * (1.0f / DMODEL) + EPS);

    #pragma unroll
    for (int i = 0; i < 3; i++) {
        const int c = tid + i * 256;
        const float y = (v[i] - mean) * rstd * g[c] + be[c];
        Y[(size_t)row * DMODEL + c] = y;
        if (Yr) Yr[(size_t)row * DMODEL + c] = f2tf32(y);
    }
}

// ---------------------------------------------------------------------------
// Launch
// ---------------------------------------------------------------------------
static float* sym_addr(const void* sym)
{
    void* p = nullptr;
    cudaGetSymbolAddress(&p, sym);
    return (float*)p;
}

extern "C" void kernel_launch(void* const* d_in, const int* in_sizes, int n_in,
                              void* d_out, int out_size)
{
    const float* x   = (const float*)d_in[0];
    // d_in[1] = mask (causal; implied)
    const float* wq  = (const float*)d_in[2];
    const float* bq  = (const float*)d_in[3];
    const float* wk  = (const float*)d_in[4];
    const float* bk  = (const float*)d_in[5];
    const float* wv  = (const float*)d_in[6];
    const float* bv  = (const float*)d_in[7];
    const float* wo  = (const float*)d_in[8];
    const float* bo  = (const float*)d_in[9];
    const float* g1  = (const float*)d_in[10];
    const float* be1 = (const float*)d_in[11];
    const float* w1  = (const float*)d_in[12];
    const float* b1  = (const float*)d_in[13];
    const float* w2  = (const float*)d_in[14];
    const float* b2  = (const float*)d_in[15];
    const float* g2  = (const float*)d_in[16];
    const float* be2 = (const float*)d_in[17];
    float* out = (float*)d_out;

    float* q   = sym_addr(g_q);
    float* k   = sym_addr(g_k);
    float* v   = sym_addr(g_v);
    float* ctx = sym_addr(g_ctx);
    float* t1  = sym_addr(g_t1);
    float* hh  = sym_addr(g_h);
    float* hr  = sym_addr(g_hr);
    float* f1  = sym_addr(g_f1);
    float* t2  = sym_addr(g_t2);
    float* xr  = sym_addr(g_xr);
    float* wqr = sym_addr(g_wqr);
    float* wkr = sym_addr(g_wkr);
    float* wvr = sym_addr(g_wvr);
    float* wor = sym_addr(g_wor);
    float* w1r = sym_addr(g_w1r);
    float* w2r = sym_addr(g_w2r);

    cudaFuncSetAttribute(attn_tc, cudaFuncAttributeMaxDynamicSharedMemorySize,
                         ATTN_SMEM);
    cudaFuncSetAttribute(gemm_ca<EP_TF32>,
                         cudaFuncAttributeMaxDynamicSharedMemorySize, GEMM_SMEM);
    cudaFuncSetAttribute(gemm_ca<EP_RESID>,
                         cudaFuncAttributeMaxDynamicSharedMemorySize, GEMM_SMEM);
    cudaFuncSetAttribute(gemm_ca<EP_GELU_TF32>,
                         cudaFuncAttributeMaxDynamicSharedMemorySize, GEMM_SMEM);

    // 0. pre-round operands to tf32
    const int nX  = MROWS * DMODEL / 4;
    const int nW  = DMODEL * DMODEL / 4;
    const int nW1 = DMODEL * DFF / 4;
    round_tf32_kernel<<<(nX  + 255)/256, 256>>>(x,  xr,  nX);
    round_tf32_kernel<<<(nW  + 255)/256, 256>>>(wq, wqr, nW);
    round_tf32_kernel<<<(nW  + 255)/256, 256>>>(wk, wkr, nW);
    round_tf32_kernel<<<(nW  + 255)/256, 256>>>(wv, wvr, nW);
    round_tf32_kernel<<<(nW  + 255)/256, 256>>>(wo, wor, nW);
    round_tf32_kernel<<<(nW1 + 255)/256, 256>>>(w1, w1r, nW1);
    round_tf32_kernel<<<(nW1 + 255)/256, 256>>>(w2, w2r, nW1);

    const dim3 gD(DMODEL/128, MROWS/128);   // 6 x 64
    const dim3 gF(DFF/128,    MROWS/128);   // 24 x 64

    // 1. QKV projections -> tf32 [B,S,H*DK] (Q pre-scaled 1/8)
    gemm_ca<EP_TF32><<<gD, 256, GEMM_SMEM>>>(xr, wqr, bq, nullptr, q, DMODEL, DMODEL, 0.125f);
    gemm_ca<EP_TF32><<<gD, 256, GEMM_SMEM>>>(xr, wkr, bk, nullptr, k, DMODEL, DMODEL, 1.0f);
    gemm_ca<EP_TF32><<<gD, 256, GEMM_SMEM>>>(xr, wvr, bv, nullptr, v, DMODEL, DMODEL, 1.0f);

    // 2. Causal flash attention -> ctx (tf32)
    attn_tc<<<dim3(SEQ/128, BATCH*NHEAD), 256, ATTN_SMEM>>>(q, k, v, ctx);

    // 3. ctx @ wo + bo + x -> t1
    gemm_ca<EP_RESID><<<gD, 256, GEMM_SMEM>>>(ctx, wor, bo, x, t1, DMODEL, DMODEL, 1.0f);

    // 4. LN1 -> h (full) + hr (tf32)
    ln_kernel<<<MROWS, 256>>>(t1, g1, be1, hh, hr);

    // 5. GELU(hr @ w1 + b1) -> f1 (tf32)
    gemm_ca<EP_GELU_TF32><<<gF, 256, GEMM_SMEM>>>(hr, w1r, b1, nullptr, f1, DFF, DMODEL, 1.0f);

    // 6. f1 @ w2 + b2 + h -> t2
    gemm_ca<EP_RESID><<<gD, 256, GEMM_SMEM>>>(f1, w2r, b2, hh, t2, DMODEL, DFF, 1.0f);

    // 7. LN2 -> out
    ln_kernel<<<MROWS, 256>>>(t2, g2, be2, out, nullptr);
}

// round 9
// speedup vs baseline: 3.7865x; 1.0276x over previous
#include <cuda_runtime.h>
#include <cuda_bf16.h>
#include <math.h>
#include <stdint.h>

// Problem constants
#define BATCH 4
#define SEQ   2048
#define DMODEL 768
#define NHEAD 12
#define DHEAD 64
#define DFF   3072
#define MROWS (BATCH*SEQ)          // 8192
#define EPS   1e-5f

// ---------------------------------------------------------------------------
// Scratch (device globals; allocation-free contract)
// ---------------------------------------------------------------------------
__device__ float g_q  [(size_t)MROWS * DMODEL];   // tf32, pre-scaled 1/8
__device__ float g_k  [(size_t)MROWS * DMODEL];   // tf32
__device__ float g_v  [(size_t)MROWS * DMODEL];   // tf32
__device__ float g_ctx[(size_t)MROWS * DMODEL];   // tf32 (attn epilogue rounds)
__device__ float g_t1 [(size_t)MROWS * DMODEL];
__device__ float g_h  [(size_t)MROWS * DMODEL];   // full fp32 (residual)
__device__ float g_hr [(size_t)MROWS * DMODEL];   // tf32 (FFN1 A operand)
__device__ float g_f1 [(size_t)MROWS * DFF];      // tf32 (GELU epilogue rounds)
__device__ float g_t2 [(size_t)MROWS * DMODEL];
// pre-rounded operands
__device__ float g_xr [(size_t)MROWS * DMODEL];
__device__ float g_wqr[(size_t)DMODEL * DMODEL];
__device__ float g_wkr[(size_t)DMODEL * DMODEL];
__device__ float g_wvr[(size_t)DMODEL * DMODEL];
__device__ float g_wor[(size_t)DMODEL * DMODEL];
__device__ float g_w1r[(size_t)DMODEL * DFF];
__device__ float g_w2r[(size_t)DFF * DMODEL];

// ---------------------------------------------------------------------------
// tf32 helpers
// ---------------------------------------------------------------------------
__device__ __forceinline__ float f2tf32(float x)
{
    uint32_t u;
    asm("cvt.rna.tf32.f32 %0, %1;" : "=r"(u) : "f"(x));
    return __uint_as_float(u);
}

__device__ __forceinline__ void mma_tf32(float* c, const uint32_t* a, const uint32_t* b)
{
    asm volatile(
        "mma.sync.aligned.m16n8k8.row.col.f32.tf32.tf32.f32 "
        "{%0,%1,%2,%3},{%4,%5,%6,%7},{%8,%9},{%0,%1,%2,%3};\n"
        : "+f"(c[0]), "+f"(c[1]), "+f"(c[2]), "+f"(c[3])
        : "r"(a[0]), "r"(a[1]), "r"(a[2]), "r"(a[3]), "r"(b[0]), "r"(b[1]));
}

__device__ __forceinline__ uint32_t smem_u32(const void* p)
{
    return (uint32_t)__cvta_generic_to_shared(p);
}

#define CPA16(dst, src) \
    asm volatile("cp.async.cg.shared.global [%0], [%1], 16;\n" :: "r"(dst), "l"(src))
#define CPA_COMMIT() asm volatile("cp.async.commit_group;\n")
#define CPA_WAIT1()  asm volatile("cp.async.wait_group 1;\n")
#define CPA_WAIT0()  asm volatile("cp.async.wait_group 0;\n")

// ---------------------------------------------------------------------------
// tf32 rounding prep kernel
// ---------------------------------------------------------------------------
__global__ __launch_bounds__(256)
void round_tf32_kernel(const float* __restrict__ src, float* __restrict__ dst, int n4)
{
    const int i = blockIdx.x * blockDim.x + threadIdx.x;
    if (i < n4) {
        float4 v = *((const float4*)src + i);
        v.x = f2tf32(v.x); v.y = f2tf32(v.y);
        v.z = f2tf32(v.z); v.w = f2tf32(v.w);
        *((float4*)dst + i) = v;
    }
}

// ---------------------------------------------------------------------------
// cp.async tf32 GEMM: C[M,N] = A[M,K] @ B[K,N] + bias (+resid / GELU->tf32 /
// tf32). Operands MUST be pre-rounded tf32 in gmem.
// BM=128 BN=128 BK=16, 256 threads (8 warps 2x4, warp tile 64x32).
// 3-stage cp.async pipeline, one sync pair per k-iter.
// A smem [m][k] pitch 20 (bank = (20g+q)%32, conflict-free).
// B smem [k][n] pitch 136 (bank = (8q+g)%32, conflict-free — fixes the
// 2-way conflict that pitch 132 had: (4q+g) ranges overlap).
// ---------------------------------------------------------------------------
enum { EP_RESID = 1, EP_GELU_TF32 = 2, EP_TF32 = 3 };

#define APITCH 20
#define ABUF   (128*APITCH)   // 2560 floats
#define BPITCH 136
#define BBUF   (16*BPITCH)    // 2176 floats
#define GEMM_SMEM ((3*ABUF + 3*BBUF) * 4)   // 56832 B

template<int EPI>
__global__ __launch_bounds__(256)
void gemm_ca(const float* __restrict__ A, const float* __restrict__ Bm,
             const float* __restrict__ bias, const float* __restrict__ resid,
             float* __restrict__ C, int Ndim, int Kdim, float oscale)
{
    extern __shared__ float gsm[];
    float* As = gsm;             // [3][128][APITCH]
    float* Bs = gsm + 3*ABUF;    // [3][16][BPITCH]

    const int tid  = threadIdx.x;
    const int lane = tid & 31;
    const int warp = tid >> 5;
    const int wm = warp & 1;
    const int wn = warp >> 1;
    const int g = lane >> 2;
    const int q = lane & 3;
    const int row0 = blockIdx.y * 128;
    const int col0 = blockIdx.x * 128;

    // cp.async mappings (256 threads)
    const int ar = tid >> 1;            // 0..127 A row
    const int ac8 = (tid & 1) * 8;      // 0 or 8 (floats)
    const int br = tid >> 4;            // 0..15 B row
    const int bc8 = (tid & 15) * 8;     // 0..120 (floats)

    const uint32_t asu = smem_u32(As);
    const uint32_t bsu = smem_u32(Bs);

    float acc[4][4][4];
    #pragma unroll
    for (int i = 0; i < 4; i++)
        #pragma unroll
        for (int j = 0; j < 4; j++)
            #pragma unroll
            for (int r = 0; r < 4; r++) acc[i][j][r] = 0.f;

    const int nk = Kdim >> 4;

    #define GISSUE(i, bf_) do {                                                   \
        const int k0_ = (i) << 4;                                                 \
        const float* asrc = A + (size_t)(row0 + ar) * Kdim + k0_ + ac8;           \
        const uint32_t ad = asu + (uint32_t)((bf_)*ABUF + ar*APITCH + ac8) * 4u;  \
        CPA16(ad,       asrc);                                                    \
        CPA16(ad + 16u, asrc + 4);                                                \
        const float* bsrc = Bm + (size_t)(k0_ + br) * Ndim + col0 + bc8;          \
        const uint32_t bd = bsu + (uint32_t)((bf_)*BBUF + br*BPITCH + bc8) * 4u;  \
        CPA16(bd,       bsrc);                                                    \
        CPA16(bd + 16u, bsrc + 4);                                                \
        CPA_COMMIT();                                                             \
    } while (0)

    #define GCOMPUTE(bf_) do {                                                    \
        const float* Ab = As + (bf_)*ABUF;                                        \
        const float* Bb = Bs + (bf_)*BBUF;                                        \
        _Pragma("unroll")                                                         \
        for (int ks = 0; ks < 16; ks += 8) {                                      \
            uint32_t af[4][4], bf2[4][2];                                         \
            _Pragma("unroll")                                                     \
            for (int mt = 0; mt < 4; mt++) {                                      \
                const int m0 = wm*64 + mt*16;                                     \
                af[mt][0] = __float_as_uint(Ab[(m0+g  )*APITCH + ks+q  ]);        \
                af[mt][1] = __float_as_uint(Ab[(m0+g+8)*APITCH + ks+q  ]);        \
                af[mt][2] = __float_as_uint(Ab[(m0+g  )*APITCH + ks+q+4]);        \
                af[mt][3] = __float_as_uint(Ab[(m0+g+8)*APITCH + ks+q+4]);        \
            }                                                                     \
            _Pragma("unroll")                                                     \
            for (int nt = 0; nt < 4; nt++) {                                      \
                const int n0 = wn*32 + nt*8;                                      \
                bf2[nt][0] = __float_as_uint(Bb[(ks+q  )*BPITCH + n0+g]);         \
                bf2[nt][1] = __float_as_uint(Bb[(ks+q+4)*BPITCH + n0+g]);         \
            }                                                                     \
            _Pragma("unroll")                                                     \
            for (int mt = 0; mt < 4; mt++)                                        \
                _Pragma("unroll")                                                 \
                for (int nt = 0; nt < 4; nt++)                                    \
                    mma_tf32(acc[mt][nt], af[mt], bf2[nt]);                       \
        }                                                                         \
    } while (0)

    GISSUE(0, 0);
    GISSUE(1, 1);

    for (int i = 0; i < nk; i++) {
        if (i + 1 < nk) { CPA_WAIT1(); } else { CPA_WAIT0(); }
        __syncthreads();
        const int cb = i % 3;
        GCOMPUTE(cb);
        if (i + 2 < nk) GISSUE(i + 2, (i + 2) % 3);
        __syncthreads();    // all warps done reading buf cb before it is reused
    }

    #undef GISSUE
    #undef GCOMPUTE

    // epilogue
    #pragma unroll
    for (int mt = 0; mt < 4; mt++) {
        const int mlo = row0 + wm*64 + mt*16 + g;
        #pragma unroll
        for (int nt = 0; nt < 4; nt++) {
            const int n = col0 + wn*32 + nt*8 + 2*q;
            const float b0 = bias[n], b1 = bias[n+1];
            #pragma unroll
            for (int half = 0; half < 2; half++) {
                const int m = mlo + half*8;
                float v0 = acc[mt][nt][half*2+0] + b0;
                float v1 = acc[mt][nt][half*2+1] + b1;
                if (EPI == EP_RESID) {
                    v0 += resid[(size_t)m * Ndim + n];
                    v1 += resid[(size_t)m * Ndim + n + 1];
                }
                if (EPI == EP_GELU_TF32) {
                    v0 = f2tf32(0.5f * v0 * (1.0f + erff(v0 * 0.70710678118654752f)));
                    v1 = f2tf32(0.5f * v1 * (1.0f + erff(v1 * 0.70710678118654752f)));
                }
                if (EPI == EP_TF32) {
                    v0 = f2tf32(v0 * oscale);
                    v1 = f2tf32(v1 * oscale);
                }
                *(float2*)(C + (size_t)m * Ndim + n) = make_float2(v0, v1);
            }
        }
    }
}

// ---------------------------------------------------------------------------
// Tensor-core flash attention (causal, tf32 mma).
// CTA = 8 warps = 128 query rows of one (b,h). 64-key tiles, cp.async x2 buf.
// ---------------------------------------------------------------------------
#define PK 68
#define PV 72
#define PP 68
#define ATTN_SMEM ((2*64*PK + 2*64*PV + 128*PP) * 4)

__global__ __launch_bounds__(256, 2)
void attn_tc(const float* __restrict__ Q, const float* __restrict__ K,
             const float* __restrict__ V, float* __restrict__ ctx)
{
    extern __shared__ float sm[];
    float* Kb[2] = { sm, sm + 64*PK };
    float* Vb[2] = { sm + 2*64*PK, sm + 2*64*PK + 64*PV };
    float* Ps    = sm + 2*64*PK + 2*64*PV;      // [128][PP], also Q staging

    const int bh = blockIdx.y;
    const int b  = bh / NHEAD;
    const int h  = bh % NHEAD;
    const int qt = (SEQ/128 - 1) - blockIdx.x;  // heavy CTAs first
    const int tid  = threadIdx.x;
    const int warp = tid >> 5;
    const int lane = tid & 31;
    const int g = lane >> 2;
    const int q = lane & 3;
    const int wrow = warp * 16;                 // 0..112
    const int qbase = qt * 128;

    const int lr = tid >> 2;                    // 0..63
    const int cb = (tid & 3) * 4;               // float4 chunk base

    const uint32_t kbu[2] = { smem_u32(Kb[0]), smem_u32(Kb[1]) };
    const uint32_t vbu[2] = { smem_u32(Vb[0]), smem_u32(Vb[1]) };

    #define ISSUE_TILE(kb, sel) do {                                                 \
        const float* kbase = K + ((size_t)(b*SEQ + (kb)*64 + lr))*DMODEL + h*DHEAD;  \
        const float* vbase = V + ((size_t)(b*SEQ + (kb)*64 + lr))*DMODEL + h*DHEAD;  \
        const uint32_t kd = kbu[sel] + (uint32_t)(lr*PK)*4u + (uint32_t)cb*16u;      \
        const uint32_t vd = vbu[sel] + (uint32_t)(lr*PV)*4u + (uint32_t)cb*16u;      \
        _Pragma("unroll")                                                            \
        for (int i = 0; i < 4; i++) {                                                \
            CPA16(kd + i*16u, kbase + (cb + i)*4);                                   \
            CPA16(vd + i*16u, vbase + (cb + i)*4);                                   \
        }                                                                            \
        CPA_COMMIT();                                                                \
    } while (0)

    ISSUE_TILE(0, 0);

    // ---- stage Q (128 rows) through Ps, read fragments into registers ----
    {
        const int qlr = tid >> 1;
        const int qlc = (tid & 1) * 8;
        const float* qsrc = Q + ((size_t)(b*SEQ + qbase + qlr))*DMODEL + h*DHEAD;
        #pragma unroll
        for (int i = 0; i < 8; i++)
            *(float4*)&Ps[qlr*PP + (qlc + i)*4] = *(const float4*)(qsrc + (qlc + i)*4);
    }
    __syncthreads();
    uint32_t qf[8][4];
    #pragma unroll
    for (int ks8 = 0; ks8 < 8; ks8++) {
        qf[ks8][0] = __float_as_uint(Ps[(wrow+g  )*PP + ks8*8 + q  ]);
        qf[ks8][1] = __float_as_uint(Ps[(wrow+g+8)*PP + ks8*8 + q  ]);
        qf[ks8][2] = __float_as_uint(Ps[(wrow+g  )*PP + ks8*8 + q+4]);
        qf[ks8][3] = __float_as_uint(Ps[(wrow+g+8)*PP + ks8*8 + q+4]);
    }
    __syncthreads();

    float oacc[8][4];
    #pragma unroll
    for (int nt = 0; nt < 8; nt++)
        #pragma unroll
        for (int e = 0; e < 4; e++) oacc[nt][e] = 0.f;
    float m0 = -1e30f, m1 = -1e30f, l0 = 0.f, l1 = 0.f;

    const int nkb = 2*qt + 2;

    for (int kb = 0; kb < nkb; kb++) {
        const int cur = kb & 1;
        if (kb + 1 < nkb) {
            ISSUE_TILE(kb + 1, cur ^ 1);
            CPA_WAIT1();
        } else {
            CPA_WAIT0();
        }
        __syncthreads();

        const bool skip = (kb*64) > (qbase + wrow + 15);
        if (!skip) {
            const float* Ksm = Kb[cur];
            const float* Vsm = Vb[cur];

            float sacc[8][4];
            #pragma unroll
            for (int nt = 0; nt < 8; nt++)
                #pragma unroll
                for (int e = 0; e < 4; e++) sacc[nt][e] = 0.f;

            #pragma unroll
            for (int ks8 = 0; ks8 < 8; ks8++) {
                const int ks = ks8 * 8;
                #pragma unroll
                for (int nt = 0; nt < 8; nt++) {
                    uint32_t bb[2];
                    bb[0] = __float_as_uint(Ksm[(nt*8+g)*PK + ks+q  ]);
                    bb[1] = __float_as_uint(Ksm[(nt*8+g)*PK + ks+q+4]);
                    mma_tf32(sacc[nt], qf[ks8], bb);
                }
            }

            if (kb*64 + 63 > qbase + wrow) {
                const int r0 = qbase + wrow + g;
                const int r1 = r0 + 8;
                #pragma unroll
                for (int nt = 0; nt < 8; nt++) {
                    const int colg = kb*64 + nt*8 + 2*q;
                    if (colg     > r0) sacc[nt][0] = -1e30f;
                    if (colg + 1 > r0) sacc[nt][1] = -1e30f;
                    if (colg     > r1) sacc[nt][2] = -1e30f;
                    if (colg + 1 > r1) sacc[nt][3] = -1e30f;
                }
            }

            float rm0 = -1e30f, rm1 = -1e30f;
            #pragma unroll
            for (int nt = 0; nt < 8; nt++) {
                rm0 = fmaxf(rm0, fmaxf(sacc[nt][0], sacc[nt][1]));
                rm1 = fmaxf(rm1, fmaxf(sacc[nt][2], sacc[nt][3]));
            }
            rm0 = fmaxf(rm0, __shfl_xor_sync(0xffffffffu, rm0, 1));
            rm0 = fmaxf(rm0, __shfl_xor_sync(0xffffffffu, rm0, 2));
            rm1 = fmaxf(rm1, __shfl_xor_sync(0xffffffffu, rm1, 1));
            rm1 = fmaxf(rm1, __shfl_xor_sync(0xffffffffu, rm1, 2));

            const float mn0 = fmaxf(m0, rm0);
            const float mn1 = fmaxf(m1, rm1);
            const float c0 = __expf(m0 - mn0);
            const float c1 = __expf(m1 - mn1);
            m0 = mn0; m1 = mn1;

            float s0 = 0.f, s1 = 0.f;
            #pragma unroll
            for (int nt = 0; nt < 8; nt++) {
                float p;
                p = __expf(sacc[nt][0] - mn0); s0 += p; sacc[nt][0] = p;
                p = __expf(sacc[nt][1] - mn0); s0 += p; sacc[nt][1] = p;
                p = __expf(sacc[nt][2] - mn1); s1 += p; sacc[nt][2] = p;
                p = __expf(sacc[nt][3] - mn1); s1 += p; sacc[nt][3] = p;
            }
            s0 += __shfl_xor_sync(0xffffffffu, s0, 1);
            s0 += __shfl_xor_sync(0xffffffffu, s0, 2);
            s1 += __shfl_xor_sync(0xffffffffu, s1, 1);
            s1 += __shfl_xor_sync(0xffffffffu, s1, 2);
            l0 = l0 * c0 + s0;
            l1 = l1 * c1 + s1;

            #pragma unroll
            for (int nt = 0; nt < 8; nt++) {
                oacc[nt][0] *= c0; oacc[nt][1] *= c0;
                oacc[nt][2] *= c1; oacc[nt][3] *= c1;
            }

            #pragma unroll
            for (int nt = 0; nt < 8; nt++) {
                *(float2*)&Ps[(wrow+g  )*PP + nt*8 + 2*q] =
                    make_float2(f2tf32(sacc[nt][0]), f2tf32(sacc[nt][1]));
                *(float2*)&Ps[(wrow+g+8)*PP + nt*8 + 2*q] =
                    make_float2(f2tf32(sacc[nt][2]), f2tf32(sacc[nt][3]));
            }
            __syncwarp();

            #pragma unroll
            for (int ks8 = 0; ks8 < 8; ks8++) {
                const int ks = ks8 * 8;
                uint32_t a[4];
                a[0] = __float_as_uint(Ps[(wrow+g  )*PP + ks+q  ]);
                a[1] = __float_as_uint(Ps[(wrow+g+8)*PP + ks+q  ]);
                a[2] = __float_as_uint(Ps[(wrow+g  )*PP + ks+q+4]);
                a[3] = __float_as_uint(Ps[(wrow+g+8)*PP + ks+q+4]);
                #pragma unroll
                for (int nt = 0; nt < 8; nt++) {
                    uint32_t bb[2];
                    bb[0] = __float_as_uint(Vsm[(ks+q  )*PV + nt*8+g]);
                    bb[1] = __float_as_uint(Vsm[(ks+q+4)*PV + nt*8+g]);
                    mma_tf32(oacc[nt], a, bb);
                }
            }
        }
        __syncthreads();
    }
    #undef ISSUE_TILE

    const float i0 = 1.f / l0;
    const float i1 = 1.f / l1;
    float* c0p = ctx + ((size_t)(b*SEQ + qbase + wrow + g    )) * DMODEL + h*DHEAD;
    float* c1p = ctx + ((size_t)(b*SEQ + qbase + wrow + g + 8)) * DMODEL + h*DHEAD;
    #pragma unroll
    for (int nt = 0; nt < 8; nt++) {
        *(float2*)(c0p + nt*8 + 2*q) =
            make_float2(f2tf32(oacc[nt][0]*i0), f2tf32(oacc[nt][1]*i0));
        *(float2*)(c1p + nt*8 + 2*q) =
            make_float2(f2tf32(oacc[nt][2]*i1), f2tf32(oacc[nt][3]*i1));
    }
}

// ---------------------------------------------------------------------------
// Row-wise LayerNorm over 768 elems. 256 threads/row.
// ---------------------------------------------------------------------------
__global__ __launch_bounds__(256)
void ln_kernel(const float* __restrict__ X, const float* __restrict__ g,
               const float* __restrict__ be, float* __restrict__ Y,
               float* __restrict__ Yr)
{
    __shared__ float red[8];
    const int row = blockIdx.x;
    const int tid = threadIdx.x;
    const float* x = X + (size_t)row * DMODEL;

    float v[3];
    float s = 0.f;
    #pragma unroll
    for (int i = 0; i < 3; i++) { v[i] = x[tid + i * 256]; s += v[i]; }

    #pragma unroll
    for (int off = 16; off; off >>= 1) s += __shfl_xor_sync(0xffffffffu, s, off);
    if ((tid & 31) == 0) red[tid >> 5] = s;
    __syncthreads();
    float total = 0.f;
    #pragma unroll
    for (int i = 0; i < 8; i++) total += red[i];
    const float mean = total * (1.0f / DMODEL);
    __syncthreads();

    float s2 = 0.f;
    #pragma unroll
    for (int i = 0; i < 3; i++) { const float d = v[i] - mean; s2 += d * d; }
    #pragma unroll
    for (int off = 16; off; off >>= 1) s2 += __shfl_xor_sync(0xffffffffu, s2, off);
    if ((tid & 31) == 0) red[tid >> 5] = s2;
    __syncthreads();
    float tot2 = 0.f;
    #pragma unroll
    for (int i = 0; i < 8; i++) tot2 += red[i];
    const float rstd = rsqrtf(tot2 * (1.0f / DMODEL) + EPS);

    #pragma unroll
    for (int i = 0; i < 3; i++) {
        const int c = tid + i * 256;
        const float y = (v[i] - mean) * rstd * g[c] + be[c];
        Y[(size_t)row * DMODEL + c] = y;
        if (Yr) Yr[(size_t)row * DMODEL + c] = f2tf32(y);
    }
}

// ---------------------------------------------------------------------------
// Launch
// ---------------------------------------------------------------------------
static float* sym_addr(const void* sym)
{
    void* p = nullptr;
    cudaGetSymbolAddress(&p, sym);
    return (float*)p;
}

extern "C" void kernel_launch(void* const* d_in, const int* in_sizes, int n_in,
                              void* d_out, int out_size)
{
    const float* x   = (const float*)d_in[0];
    // d_in[1] = mask (causal; implied)
    const float* wq  = (const float*)d_in[2];
    const float* bq  = (const float*)d_in[3];
    const float* wk  = (const float*)d_in[4];
    const float* bk  = (const float*)d_in[5];
    const float* wv  = (const float*)d_in[6];
    const float* bv  = (const float*)d_in[7];
    const float* wo  = (const float*)d_in[8];
    const float* bo  = (const float*)d_in[9];
    const float* g1  = (const float*)d_in[10];
    const float* be1 = (const float*)d_in[11];
    const float* w1  = (const float*)d_in[12];
    const float* b1  = (const float*)d_in[13];
    const float* w2  = (const float*)d_in[14];
    const float* b2  = (const float*)d_in[15];
    const float* g2  = (const float*)d_in[16];
    const float* be2 = (const float*)d_in[17];
    float* out = (float*)d_out;

    float* q   = sym_addr(g_q);
    float* k   = sym_addr(g_k);
    float* v   = sym_addr(g_v);
    float* ctx = sym_addr(g_ctx);
    float* t1  = sym_addr(g_t1);
    float* hh  = sym_addr(g_h);
    float* hr  = sym_addr(g_hr);
    float* f1  = sym_addr(g_f1);
    float* t2  = sym_addr(g_t2);
    float* xr  = sym_addr(g_xr);
    float* wqr = sym_addr(g_wqr);
    float* wkr = sym_addr(g_wkr);
    float* wvr = sym_addr(g_wvr);
    float* wor = sym_addr(g_wor);
    float* w1r = sym_addr(g_w1r);
    float* w2r = sym_addr(g_w2r);

    cudaFuncSetAttribute(attn_tc, cudaFuncAttributeMaxDynamicSharedMemorySize,
                         ATTN_SMEM);
    cudaFuncSetAttribute(gemm_ca<EP_TF32>,
                         cudaFuncAttributeMaxDynamicSharedMemorySize, GEMM_SMEM);
    cudaFuncSetAttribute(gemm_ca<EP_RESID>,
                         cudaFuncAttributeMaxDynamicSharedMemorySize, GEMM_SMEM);
    cudaFuncSetAttribute(gemm_ca<EP_GELU_TF32>,
                         cudaFuncAttributeMaxDynamicSharedMemorySize, GEMM_SMEM);

    // 0. pre-round operands to tf32
    const int nX  = MROWS * DMODEL / 4;
    const int nW  = DMODEL * DMODEL / 4;
    const int nW1 = DMODEL * DFF / 4;
    round_tf32_kernel<<<(nX  + 255)/256, 256>>>(x,  xr,  nX);
    round_tf32_kernel<<<(nW  + 255)/256, 256>>>(wq, wqr, nW);
    round_tf32_kernel<<<(nW  + 255)/256, 256>>>(wk, wkr, nW);
    round_tf32_kernel<<<(nW  + 255)/256, 256>>>(wv, wvr, nW);
    round_tf32_kernel<<<(nW  + 255)/256, 256>>>(wo, wor, nW);
    round_tf32_kernel<<<(nW1 + 255)/256, 256>>>(w1, w1r, nW1);
    round_tf32_kernel<<<(nW1 + 255)/256, 256>>>(w2, w2r, nW1);

    const dim3 gD(DMODEL/128, MROWS/128);   // 6 x 64
    const dim3 gF(DFF/128,    MROWS/128);   // 24 x 64

    // 1. QKV projections -> tf32 [B,S,H*DK] (Q pre-scaled 1/8)
    gemm_ca<EP_TF32><<<gD, 256, GEMM_SMEM>>>(xr, wqr, bq, nullptr, q, DMODEL, DMODEL, 0.125f);
    gemm_ca<EP_TF32><<<gD, 256, GEMM_SMEM>>>(xr, wkr, bk, nullptr, k, DMODEL, DMODEL, 1.0f);
    gemm_ca<EP_TF32><<<gD, 256, GEMM_SMEM>>>(xr, wvr, bv, nullptr, v, DMODEL, DMODEL, 1.0f);

    // 2. Causal flash attention -> ctx (tf32)
    attn_tc<<<dim3(SEQ/128, BATCH*NHEAD), 256, ATTN_SMEM>>>(q, k, v, ctx);

    // 3. ctx @ wo + bo + x -> t1
    gemm_ca<EP_RESID><<<gD, 256, GEMM_SMEM>>>(ctx, wor, bo, x, t1, DMODEL, DMODEL, 1.0f);

    // 4. LN1 -> h (full) + hr (tf32)
    ln_kernel<<<MROWS, 256>>>(t1, g1, be1, hh, hr);

    // 5. GELU(hr @ w1 + b1) -> f1 (tf32)
    gemm_ca<EP_GELU_TF32><<<gF, 256, GEMM_SMEM>>>(hr, w1r, b1, nullptr, f1, DFF, DMODEL, 1.0f);

    // 6. f1 @ w2 + b2 + h -> t2
    gemm_ca<EP_RESID><<<gD, 256, GEMM_SMEM>>>(f1, w2r, b2, hh, t2, DMODEL, DFF, 1.0f);

    // 7. LN2 -> out
    ln_kernel<<<MROWS, 256>>>(t2, g2, be2, out, nullptr);
}